// round 13
// baseline (speedup 1.0000x reference)
#include <cuda_runtime.h>
#include <cuda_fp16.h>
#include <math.h>
#include <stdint.h>

// ---------------- problem constants ----------------
#define BB   4
#define SVL  1024
#define SEX  64
#define SS   1088
#define DVL  2048
#define DEX  1024
#define HQ   16
#define HKV  8
#define DH   128
#define IVL  6144
#define IEX  3072
#define MVL  (BB*SVL)      // 4096
#define MEX  (BB*SEX)      // 256
#define EPSV 1e-6f
#define ATT_SCALE 0.08838834764831845f
#define LOG2_THETA 22.253496664211536f

typedef __half fp16;

// ---------------- low-level helpers ----------------
__device__ __forceinline__ uint32_t smem_u32(const void* p) {
    uint32_t a;
    asm("{ .reg .u64 t; cvta.to.shared.u64 t, %1; cvt.u32.u64 %0, t; }" : "=r"(a) : "l"(p));
    return a;
}
__device__ __forceinline__ void ldsm4(uint32_t* r, uint32_t addr) {
    asm volatile("ldmatrix.sync.aligned.m8n8.x4.shared.b16 {%0,%1,%2,%3}, [%4];"
                 : "=r"(r[0]), "=r"(r[1]), "=r"(r[2]), "=r"(r[3]) : "r"(addr));
}
__device__ __forceinline__ void mma_f16(float* c, const uint32_t* a, const uint32_t* b) {
    asm("mma.sync.aligned.m16n8k16.row.col.f32.f16.f16.f32 "
        "{%0,%1,%2,%3}, {%4,%5,%6,%7}, {%8,%9}, {%0,%1,%2,%3};"
        : "+f"(c[0]), "+f"(c[1]), "+f"(c[2]), "+f"(c[3])
        : "r"(a[0]), "r"(a[1]), "r"(a[2]), "r"(a[3]), "r"(b[0]), "r"(b[1]));
}
__device__ __forceinline__ void cpasync16(uint32_t dst, const void* src) {
    asm volatile("cp.async.cg.shared.global [%0], [%1], 16;" :: "r"(dst), "l"(src));
}
__device__ __forceinline__ void split2h(float v, fp16& h, fp16& l) {
    h = __float2half(v);
    l = __float2half(v - __half2float(h));
}
__device__ __forceinline__ float silu_f(float g) {
    return g / (1.f + __expf(-g));
}

// ---------------- device scratch ----------------
__device__ fp16 g_vl_wqkvT[4096u*2048u];
__device__ fp16 g_ex_wqkvT[4096u*1024u];
__device__ fp16 g_vl_woT[2048u*2048u];
__device__ fp16 g_ex_woT[1024u*2048u];
__device__ fp16 g_vl_wguT[12288u*2048u];   // 8-col interleaved g/u packing
__device__ fp16 g_ex_wguT[6144u*1024u];
__device__ fp16 g_vl_wdT[2048u*6144u];
__device__ fp16 g_ex_wdT[1024u*3072u];
__device__ fp16 g_X1s[2][(size_t)MVL*DVL];
__device__ fp16 g_X2s[2][(size_t)MEX*DEX];
__device__ fp16 g_A1s[2][(size_t)MVL*(HQ*DH)];
__device__ fp16 g_A2s[2][(size_t)MEX*(HQ*DH)];
__device__ fp16 g_GU1s[2][(size_t)MVL*IVL];
__device__ fp16 g_GU2s[2][(size_t)MEX*IEX];
__device__ float g_QKV1[(size_t)MVL*4096u];
__device__ float g_QKV2[(size_t)MEX*4096u];
__device__ float g_O1[(size_t)MVL*DVL];
__device__ float g_O2[(size_t)MEX*DEX];
__device__ fp16 g_Qh[(size_t)BB*HQ*SS*DH];
__device__ fp16 g_Kh[(size_t)BB*HKV*SS*DH];
__device__ fp16 g_Vt[(size_t)BB*HKV*DH*SS];

// ---------------- transpose: W[K][N] -> T[N][K] fp16, optional row map ----------
__global__ __launch_bounds__(256) void tsplit_k(const float* __restrict__ W,
                                                fp16* __restrict__ T,
                                                int K, int N, int mode)
{
    __shared__ float t[32][33];
    const int n0 = blockIdx.x * 32, k0 = blockIdx.y * 32;
    const int tx = threadIdx.x, ty = threadIdx.y;
    #pragma unroll
    for (int j = 0; j < 4; j++)
        t[ty + 8 * j][tx] = W[(size_t)(k0 + ty + 8 * j) * N + n0 + tx];
    __syncthreads();
    #pragma unroll
    for (int j = 0; j < 4; j++) {
        const int n = n0 + ty + 8 * j;
        int p = n;
        if (mode == 1) p = ((n >> 3) << 4) | (n & 7);
        else if (mode == 2) p = ((n >> 3) << 4) | 8 | (n & 7);
        T[(size_t)p * K + k0 + tx] = __float2half(t[tx][ty + 8 * j]);
    }
}

// ---------------- merged QKV weight transpose ----------------
__global__ __launch_bounds__(256) void tsplit_qkv_k(const float* __restrict__ Wq,
                                                    const float* __restrict__ Wk,
                                                    const float* __restrict__ Wv,
                                                    fp16* __restrict__ T, int K)
{
    __shared__ float t[32][33];
    const int n0 = blockIdx.x * 32, k0 = blockIdx.y * 32;
    const int tx = threadIdx.x, ty = threadIdx.y;
    const float* W; int nb, Ns;
    if (n0 < 2048)      { W = Wq; nb = n0;        Ns = 2048; }
    else if (n0 < 3072) { W = Wk; nb = n0 - 2048; Ns = 1024; }
    else                { W = Wv; nb = n0 - 3072; Ns = 1024; }
    #pragma unroll
    for (int j = 0; j < 4; j++)
        t[ty + 8 * j][tx] = W[(size_t)(k0 + ty + 8 * j) * Ns + nb + tx];
    __syncthreads();
    #pragma unroll
    for (int j = 0; j < 4; j++)
        T[(size_t)(n0 + ty + 8 * j) * K + k0 + tx] = __float2half(t[tx][ty + 8 * j]);
}

// ---------------- rmsnorm -> fp16 hi/lo ----------------
__global__ __launch_bounds__(256) void rmsnorm_split_k(const float* __restrict__ x,
                                                       const float* __restrict__ w,
                                                       fp16* __restrict__ yh, fp16* __restrict__ yl,
                                                       int D)
{
    const int row = blockIdx.x;
    const float* xr = x + (size_t)row * D;
    float s = 0.f;
    for (int i = threadIdx.x; i < D; i += 256) { float v = xr[i]; s += v * v; }
    #pragma unroll
    for (int o = 16; o; o >>= 1) s += __shfl_xor_sync(0xffffffffu, s, o);
    __shared__ float ws[8];
    if ((threadIdx.x & 31) == 0) ws[threadIdx.x >> 5] = s;
    __syncthreads();
    float tot = 0.f;
    #pragma unroll
    for (int i = 0; i < 8; i++) tot += ws[i];
    const float r = rsqrtf(tot / (float)D + EPSV);
    for (int i = threadIdx.x; i < D; i += 256) {
        float v = xr[i] * r * w[i];
        fp16 h, l; split2h(v, h, l);
        yh[(size_t)row * D + i] = h;
        yl[(size_t)row * D + i] = l;
    }
}

// ---------------- head rmsnorm + RoPE -> fp16 [B,H,SS,DH] ----------------
__global__ __launch_bounds__(128) void qkv_post_k(const float* __restrict__ raw,
                                                  int rowStride,
                                                  const float* __restrict__ w,
                                                  const int* __restrict__ pos_ids,
                                                  fp16* __restrict__ out,
                                                  int H, int sCount, int seqOff,
                                                  float outScale)
{
    __shared__ float sh[DH];
    __shared__ float ws[4];
    const int d = threadIdx.x;
    const int s = blockIdx.x, h = blockIdx.y, b = blockIdx.z;
    const int row = b * sCount + s;
    float v = raw[(size_t)row * rowStride + h * DH + d];
    {
        float v2 = v * v;
        #pragma unroll
        for (int o = 16; o; o >>= 1) v2 += __shfl_xor_sync(0xffffffffu, v2, o);
        if ((d & 31) == 0) ws[d >> 5] = v2;
        __syncthreads();
        float tot = ws[0] + ws[1] + ws[2] + ws[3];
        v = v * rsqrtf(tot * (1.0f / DH) + EPSV) * w[d];
    }
    const int gs = seqOff + s;
    {
        sh[d] = v;
        __syncthreads();
        const float partner = (d < 64) ? -sh[d + 64] : sh[d - 64];
        const int pos = pos_ids[b * SS + gs];
        const float fr = (float)(d & 63) * (1.0f / 64.0f);
        const float invf = exp2f(-fr * LOG2_THETA);
        float sn, cs;
        sincosf((float)pos * invf, &sn, &cs);
        v = v * cs + partner * sn;
    }
    out[(((size_t)b * H + h) * SS + gs) * DH + d] = __float2half(v * outScale);
}

// ---------------- V transpose ----------------
__global__ __launch_bounds__(256) void vtrans_k(const float* __restrict__ qkv, int rowStride,
                                                fp16* __restrict__ Vt, int sCount, int seqOff)
{
    __shared__ float t[32][33];
    const int s0 = blockIdx.x * 32, d0 = blockIdx.y * 32, z = blockIdx.z;
    const int b = z / HKV, h = z - b * HKV;
    const int tx = threadIdx.x, ty = threadIdx.y;
    #pragma unroll
    for (int j = 0; j < 4; j++) {
        const int s = s0 + ty + 8 * j;
        t[ty + 8 * j][tx] = qkv[(size_t)(b * sCount + s) * rowStride + 3072 + h * DH + d0 + tx];
    }
    __syncthreads();
    #pragma unroll
    for (int j = 0; j < 4; j++) {
        const int d = d0 + ty + 8 * j;
        Vt[((size_t)z * DH + d) * SS + seqOff + s0 + tx] = __float2half(t[tx][ty + 8 * j]);
    }
}

// ---------------- fp16 2-term warp-MMA GEMM ----------------
// CTA 128x256, 512 threads (16 warps, 4x4), warp tile 32x64, KC=64, 3-stage ring.
#define KC 64
#define ROWB 144
#define A_BYTES (128*ROWB)
#define B_BYTES (256*ROWB)
#define STAGE_BYTES (2*A_BYTES + B_BYTES)
#define NSTAGE 3
#define GEMM_SMEM (NSTAGE*STAGE_BYTES)

__device__ __forceinline__ void g_load_stage(uint32_t sb,
    const fp16* __restrict__ Ah, const fp16* __restrict__ Al,
    const fp16* __restrict__ B,
    int bm, int bn, int K, int k0, int tid)
{
    #pragma unroll
    for (int it = 0; it < 2; it++) {
        const int id = tid + it * 512;
        const int row = id >> 3, col = id & 7;
        const uint32_t so = (uint32_t)row * ROWB + col * 16;
        const size_t ga = (size_t)(bm + row) * K + k0 + col * 8;
        cpasync16(sb + so,           Ah + ga);
        cpasync16(sb + A_BYTES + so, Al + ga);
    }
    #pragma unroll
    for (int it = 0; it < 4; it++) {
        const int id = tid + it * 512;
        const int row = id >> 3, col = id & 7;
        const uint32_t so = (uint32_t)row * ROWB + col * 16;
        const size_t gb = (size_t)(bn + row) * K + k0 + col * 8;
        cpasync16(sb + 2*A_BYTES + so, B + gb);
    }
    asm volatile("cp.async.commit_group;" ::: "memory");
}

template<int FUSE>
__global__ __launch_bounds__(512, 1)
void mmagemm_k(const fp16* __restrict__ Ah, const fp16* __restrict__ Al,
               const fp16* __restrict__ B,
               const float* __restrict__ R, float* __restrict__ C,
               fp16* __restrict__ oh, fp16* __restrict__ ol,
               int N, int K, int Nout)
{
    extern __shared__ char smem[];
    const uint32_t smem_base = smem_u32(smem);
    const int tid = threadIdx.x;
    const int lane = tid & 31, warp = tid >> 5;
    const int wm = warp >> 2, wn = warp & 3;           // 4 x 4 warp grid
    const int bm = blockIdx.y * 128, bn = blockIdx.x * 256;

    float acc[16][4];
    #pragma unroll
    for (int i = 0; i < 16; i++)
        #pragma unroll
        for (int j = 0; j < 4; j++) acc[i][j] = 0.f;

    const int laneRA = (lane & 7) + ((lane >> 3) & 1) * 8;
    const int laneCA = (lane >> 4) * 8;
    const int jmB = lane >> 3;
    const int laneRB = (jmB >> 1) * 8 + (lane & 7);
    const int laneCB = (jmB & 1) * 8;

    const int nst = K / KC;
    g_load_stage(smem_base, Ah, Al, B, bm, bn, K, 0, tid);
    g_load_stage(smem_base + STAGE_BYTES, Ah, Al, B, bm, bn, K, KC, tid);

    for (int s = 0; s < nst; s++) {
        if (s + 2 < nst)
            g_load_stage(smem_base + ((s + 2) % NSTAGE) * STAGE_BYTES,
                         Ah, Al, B, bm, bn, K, (s + 2) * KC, tid);
        else
            asm volatile("cp.async.commit_group;" ::: "memory");
        asm volatile("cp.async.wait_group 2;" ::: "memory");
        __syncthreads();

        const uint32_t sb = smem_base + (s % NSTAGE) * STAGE_BYTES;
        #pragma unroll
        for (int kk = 0; kk < KC; kk += 16) {
            uint32_t bf[4][4];
            #pragma unroll
            for (int j = 0; j < 4; j++) {
                const uint32_t off = (uint32_t)(wn*64 + j*16 + laneRB) * ROWB
                                   + 2 * (laneCB + kk);
                ldsm4(bf[j], sb + 2*A_BYTES + off);
            }
            #pragma unroll
            for (int i = 0; i < 2; i++) {
                uint32_t ah[4], al[4];
                const uint32_t offA = (uint32_t)(wm*32 + i*16 + laneRA) * ROWB
                                    + 2 * (laneCA + kk);
                ldsm4(ah, sb + offA);
                ldsm4(al, sb + A_BYTES + offA);
                #pragma unroll
                for (int j = 0; j < 8; j++)
                    mma_f16(acc[i*8 + j], ah, &bf[j >> 1][(j & 1) * 2]);
                #pragma unroll
                for (int j = 0; j < 8; j++)
                    mma_f16(acc[i*8 + j], al, &bf[j >> 1][(j & 1) * 2]);
            }
        }
        __syncthreads();
    }

    if (!FUSE) {
        #pragma unroll
        for (int i = 0; i < 2; i++) {
            const int mrow = bm + wm*32 + i*16 + (lane >> 2);
            #pragma unroll
            for (int j = 0; j < 8; j++) {
                const int ncol = bn + wn*64 + j*8 + (lane & 3)*2;
                const float* a = acc[i*8 + j];
                const size_t i0 = (size_t)mrow * N + ncol;
                const size_t i1 = (size_t)(mrow + 8) * N + ncol;
                float2 v0 = make_float2(a[0], a[1]);
                float2 v1 = make_float2(a[2], a[3]);
                if (R) {
                    float2 r0 = *(const float2*)(R + i0);
                    float2 r1 = *(const float2*)(R + i1);
                    v0.x += r0.x; v0.y += r0.y;
                    v1.x += r1.x; v1.y += r1.y;
                }
                *(float2*)(C + i0) = v0;
                *(float2*)(C + i1) = v1;
            }
        }
    } else {
        #pragma unroll
        for (int i = 0; i < 2; i++) {
            const int mrow = bm + wm*32 + i*16 + (lane >> 2);
            #pragma unroll
            for (int t = 0; t < 4; t++) {
                const float* g = acc[i*8 + 2*t];
                const float* u = acc[i*8 + 2*t + 1];
                const int ncol = (bn >> 1) + wn*32 + t*8 + (lane & 3)*2;
                float v0 = silu_f(g[0]) * u[0];
                float v1 = silu_f(g[1]) * u[1];
                float v2 = silu_f(g[2]) * u[2];
                float v3 = silu_f(g[3]) * u[3];
                fp16 h0,l0,h1,l1,h2,l2,h3,l3;
                split2h(v0,h0,l0); split2h(v1,h1,l1);
                split2h(v2,h2,l2); split2h(v3,h3,l3);
                const size_t i0 = (size_t)mrow * Nout + ncol;
                const size_t i1 = (size_t)(mrow + 8) * Nout + ncol;
                *(__half2*)(oh + i0) = __half2(h0, h1);
                *(__half2*)(ol + i0) = __half2(l0, l1);
                *(__half2*)(oh + i1) = __half2(h2, h3);
                *(__half2*)(ol + i1) = __half2(l2, l3);
            }
        }
    }
}

// ---------------- tensor-core flash attention ----------------
#define TBK 64
#define QK_ROWB 272
#define VT_ROWB 144
#define QTILE_B (64*QK_ROWB)
#define KTILE_B (64*QK_ROWB)
#define VTILE_B (128*VT_ROWB)
#define AT_STAGE (KTILE_B + VTILE_B)
#define ATTN_SMEM (QTILE_B + 2*AT_STAGE)

__device__ __forceinline__ void attn_load_stage(uint32_t sb, const fp16* __restrict__ Kb,
                                                const fp16* __restrict__ Vb, int k0, int tid)
{
    #pragma unroll
    for (int it = 0; it < 8; it++) {
        const int id = tid + it * 128;
        const int row = id >> 4, col = id & 15;
        cpasync16(sb + (uint32_t)row * QK_ROWB + col * 16,
                  Kb + (size_t)(k0 + row) * DH + col * 8);
    }
    #pragma unroll
    for (int it = 0; it < 8; it++) {
        const int id = tid + it * 128;
        const int row = id >> 3, col = id & 7;
        cpasync16(sb + KTILE_B + (uint32_t)row * VT_ROWB + col * 16,
                  Vb + (size_t)row * SS + k0 + col * 8);
    }
    asm volatile("cp.async.commit_group;" ::: "memory");
}

__global__ __launch_bounds__(128) void attn_k(const fp16* __restrict__ Qg,
                                              const fp16* __restrict__ Kg,
                                              const fp16* __restrict__ Vtg,
                                              fp16* __restrict__ a1h, fp16* __restrict__ a1l,
                                              fp16* __restrict__ a2h, fp16* __restrict__ a2l)
{
    extern __shared__ char smem[];
    const uint32_t sQ = smem_u32(smem);
    const int tid = threadIdx.x;
    const int lane = tid & 31, w = tid >> 5;
    const int b = blockIdx.z, h = blockIdx.y;
    const int q0 = blockIdx.x * 64;
    const int kvh = h >> 1;
    const fp16* Qb = Qg + ((size_t)(b * HQ + h) * SS + q0) * DH;
    const fp16* Kb = Kg + (size_t)(b * HKV + kvh) * SS * DH;
    const fp16* Vb = Vtg + (size_t)(b * HKV + kvh) * DH * SS;

    const int nt = (q0 < SVL) ? (SVL / TBK) : (SS / TBK);

    #pragma unroll
    for (int it = 0; it < 8; it++) {
        const int id = tid + it * 128;
        const int row = id >> 4, col = id & 15;
        cpasync16(sQ + (uint32_t)row * QK_ROWB + col * 16, Qb + (size_t)row * DH + col * 8);
    }
    attn_load_stage(sQ + QTILE_B, Kb, Vb, 0, tid);

    const int laneRA = (lane & 7) + ((lane >> 3) & 1) * 8;
    const int laneCA = (lane >> 4) * 8;
    const int jmB = lane >> 3;
    const int laneRB = (jmB >> 1) * 8 + (lane & 7);
    const int laneCB = (jmB & 1) * 8;

    float o[16][4];
    #pragma unroll
    for (int n = 0; n < 16; n++)
        #pragma unroll
        for (int j = 0; j < 4; j++) o[n][j] = 0.f;
    float m0 = -1e30f, m1 = -1e30f, l0 = 0.f, l1 = 0.f;

    int buf = 0;
    for (int t = 0; t < nt; t++) {
        if (t + 1 < nt) {
            attn_load_stage(sQ + QTILE_B + (buf ^ 1) * AT_STAGE, Kb, Vb, (t + 1) * TBK, tid);
            asm volatile("cp.async.wait_group 1;" ::: "memory");
        } else {
            asm volatile("cp.async.wait_group 0;" ::: "memory");
        }
        __syncthreads();

        const uint32_t sK = sQ + QTILE_B + buf * AT_STAGE;
        const uint32_t sV = sK + KTILE_B;
        const int k0 = t * TBK;

        float s[8][4];
        #pragma unroll
        for (int j = 0; j < 8; j++) { s[j][0]=0.f; s[j][1]=0.f; s[j][2]=0.f; s[j][3]=0.f; }
        #pragma unroll
        for (int kk = 0; kk < 8; kk++) {
            uint32_t qa[4];
            ldsm4(qa, sQ + (uint32_t)(w*16 + laneRA) * QK_ROWB + 2 * (laneCA + kk*16));
            #pragma unroll
            for (int jj = 0; jj < 4; jj++) {
                uint32_t kb[4];
                ldsm4(kb, sK + (uint32_t)(jj*16 + laneRB) * QK_ROWB + 2 * (laneCB + kk*16));
                mma_f16(s[2*jj],   qa, &kb[0]);
                mma_f16(s[2*jj+1], qa, &kb[2]);
            }
        }

        if (k0 >= SVL) {
            const int qr0 = q0 + w*16 + (lane >> 2);
            #pragma unroll
            for (int j = 0; j < 8; j++) {
                const int kc = k0 + j*8 + 2*(lane & 3);
                if (kc   > qr0)     s[j][0] = -1e9f;
                if (kc+1 > qr0)     s[j][1] = -1e9f;
                if (kc   > qr0 + 8) s[j][2] = -1e9f;
                if (kc+1 > qr0 + 8) s[j][3] = -1e9f;
            }
        }

        float mx0 = m0, mx1 = m1;
        #pragma unroll
        for (int j = 0; j < 8; j++) {
            mx0 = fmaxf(mx0, fmaxf(s[j][0], s[j][1]));
            mx1 = fmaxf(mx1, fmaxf(s[j][2], s[j][3]));
        }
        mx0 = fmaxf(mx0, __shfl_xor_sync(0xffffffffu, mx0, 1));
        mx0 = fmaxf(mx0, __shfl_xor_sync(0xffffffffu, mx0, 2));
        mx1 = fmaxf(mx1, __shfl_xor_sync(0xffffffffu, mx1, 1));
        mx1 = fmaxf(mx1, __shfl_xor_sync(0xffffffffu, mx1, 2));
        const float corr0 = __expf(m0 - mx0), corr1 = __expf(m1 - mx1);
        m0 = mx0; m1 = mx1;
        l0 *= corr0; l1 *= corr1;
        #pragma unroll
        for (int n = 0; n < 16; n++) {
            o[n][0] *= corr0; o[n][1] *= corr0;
            o[n][2] *= corr1; o[n][3] *= corr1;
        }

        uint32_t pf[4][4];
        #pragma unroll
        for (int j = 0; j < 8; j++) {
            const float p0 = __expf(s[j][0] - mx0);
            const float p1 = __expf(s[j][1] - mx0);
            const float p2 = __expf(s[j][2] - mx1);
            const float p3 = __expf(s[j][3] - mx1);
            l0 += p0 + p1; l1 += p2 + p3;
            __half2 ha = __floats2half2_rn(p0, p1);
            __half2 hb = __floats2half2_rn(p2, p3);
            const int tt = j >> 1, o2 = (j & 1) * 2;
            pf[tt][o2]     = *(uint32_t*)&ha;
            pf[tt][o2 + 1] = *(uint32_t*)&hb;
        }

        #pragma unroll
        for (int tt = 0; tt < 4; tt++) {
            #pragma unroll
            for (int jj = 0; jj < 8; jj++) {
                uint32_t vb[4];
                ldsm4(vb, sV + (uint32_t)(jj*16 + laneRB) * VT_ROWB + 2 * (laneCB + tt*16));
                mma_f16(o[2*jj],   pf[tt], &vb[0]);
                mma_f16(o[2*jj+1], pf[tt], &vb[2]);
            }
        }
        __syncthreads();
        buf ^= 1;
    }

    l0 += __shfl_xor_sync(0xffffffffu, l0, 1);
    l0 += __shfl_xor_sync(0xffffffffu, l0, 2);
    l1 += __shfl_xor_sync(0xffffffffu, l1, 1);
    l1 += __shfl_xor_sync(0xffffffffu, l1, 2);
    const float li0 = 1.f / l0, li1 = 1.f / l1;
    const int qr0 = q0 + w*16 + (lane >> 2);
    #pragma unroll
    for (int n = 0; n < 16; n++) {
        const int col = h * DH + n*8 + 2*(lane & 3);
        #pragma unroll
        for (int half = 0; half < 2; half++) {
            const int qr = qr0 + half * 8;
            const float va = o[n][half*2]     * (half ? li1 : li0);
            const float vb2 = o[n][half*2 + 1] * (half ? li1 : li0);
            fp16 ha, la, hb, lb;
            split2h(va, ha, la);
            split2h(vb2, hb, lb);
            size_t idx;
            fp16 *oh, *ol;
            if (qr < SVL) { idx = (size_t)(b * SVL + qr) * (HQ*DH) + col; oh = a1h; ol = a1l; }
            else          { idx = (size_t)(b * SEX + qr - SVL) * (HQ*DH) + col; oh = a2h; ol = a2l; }
            *(__half2*)(oh + idx) = __half2(ha, hb);
            *(__half2*)(ol + idx) = __half2(la, lb);
        }
    }
}

// ---------------- launch ----------------
extern "C" void kernel_launch(void* const* d_in, const int* in_sizes, int n_in,
                              void* d_out, int out_size)
{
    (void)in_sizes; (void)n_in; (void)out_size;
    const float* hs_vl  = (const float*)d_in[0];
    const float* hs_ex  = (const float*)d_in[1];
    const int*   posids = (const int*)  d_in[2];
    const float* vl_ln1 = (const float*)d_in[4];
    const float* vl_wq  = (const float*)d_in[5];
    const float* vl_wk  = (const float*)d_in[6];
    const float* vl_wv  = (const float*)d_in[7];
    const float* vl_qn  = (const float*)d_in[8];
    const float* vl_kn  = (const float*)d_in[9];
    const float* vl_wo  = (const float*)d_in[10];
    const float* vl_ln2 = (const float*)d_in[11];
    const float* vl_wg  = (const float*)d_in[12];
    const float* vl_wu  = (const float*)d_in[13];
    const float* vl_wd  = (const float*)d_in[14];
    const float* ex_ln1 = (const float*)d_in[15];
    const float* ex_wq  = (const float*)d_in[16];
    const float* ex_wk  = (const float*)d_in[17];
    const float* ex_wv  = (const float*)d_in[18];
    const float* ex_qn  = (const float*)d_in[19];
    const float* ex_kn  = (const float*)d_in[20];
    const float* ex_wo  = (const float*)d_in[21];
    const float* ex_ln2 = (const float*)d_in[22];
    const float* ex_wg  = (const float*)d_in[23];
    const float* ex_wu  = (const float*)d_in[24];
    const float* ex_wd  = (const float*)d_in[25];

    float* out_vl = (float*)d_out;
    float* out_ex = out_vl + (size_t)MVL * DVL;

#define SYM(T, p, s) T* p; cudaGetSymbolAddress((void**)&p, s)
    SYM(fp16, vl_wqkvT, g_vl_wqkvT); SYM(fp16, ex_wqkvT, g_ex_wqkvT);
    SYM(fp16, vl_woT, g_vl_woT);     SYM(fp16, ex_woT, g_ex_woT);
    SYM(fp16, vl_wguT, g_vl_wguT);   SYM(fp16, ex_wguT, g_ex_wguT);
    SYM(fp16, vl_wdT, g_vl_wdT);     SYM(fp16, ex_wdT, g_ex_wdT);
    SYM(fp16, X1s, g_X1s); SYM(fp16, X2s, g_X2s);
    SYM(fp16, A1s, g_A1s); SYM(fp16, A2s, g_A2s);
    SYM(fp16, GU1s, g_GU1s); SYM(fp16, GU2s, g_GU2s);
    SYM(float, QKV1, g_QKV1); SYM(float, QKV2, g_QKV2);
    SYM(fp16, Qh, g_Qh); SYM(fp16, Kh, g_Kh); SYM(fp16, Vt, g_Vt);
    SYM(float, O1, g_O1); SYM(float, O2, g_O2);
#undef SYM

    cudaFuncSetAttribute(mmagemm_k<0>, cudaFuncAttributeMaxDynamicSharedMemorySize, GEMM_SMEM);
    cudaFuncSetAttribute(mmagemm_k<1>, cudaFuncAttributeMaxDynamicSharedMemorySize, GEMM_SMEM);
    cudaFuncSetAttribute(attn_k, cudaFuncAttributeMaxDynamicSharedMemorySize, ATTN_SMEM);

#define TS(W, T, ROFF, KK, NN, MODE) \
    tsplit_k<<<dim3((NN)/32, (KK)/32), dim3(32, 8)>>>(W, (T) + (size_t)(ROFF)*(KK), KK, NN, MODE)
#define TG(FUSE, AH, AL, BT, Rr, Cc, OH, OL, M, N, K, NOUT) \
    mmagemm_k<FUSE><<<dim3((N)/256, (M)/128), 512, GEMM_SMEM>>>( \
        AH, AL, BT, Rr, Cc, OH, OL, N, K, NOUT)

    const size_t NX1 = (size_t)MVL * DVL, NX2 = (size_t)MEX * DEX;
    const size_t NA1 = (size_t)MVL * (HQ * DH), NA2 = (size_t)MEX * (HQ * DH);
    const size_t NG1 = (size_t)MVL * IVL, NG2 = (size_t)MEX * IEX;

    // launches 0-2: deps of the big GEMM; launch 3 = VL QKV GEMM (ncu captures idx 3)
    tsplit_qkv_k<<<dim3(4096/32, 2048/32), dim3(32, 8)>>>(vl_wq, vl_wk, vl_wv, vl_wqkvT, 2048);
    rmsnorm_split_k<<<MVL, 256>>>(hs_vl, vl_ln1, X1s, X1s + NX1, DVL);
    rmsnorm_split_k<<<MEX, 256>>>(hs_ex, ex_ln1, X2s, X2s + NX2, DEX);
    TG(0, X1s, X1s + NX1, vl_wqkvT, nullptr, QKV1, (fp16*)nullptr, (fp16*)nullptr, MVL, 4096, 2048, 0);

    // remaining weight transforms
    tsplit_qkv_k<<<dim3(4096/32, 1024/32), dim3(32, 8)>>>(ex_wq, ex_wk, ex_wv, ex_wqkvT, 1024);
    TS(vl_wo, vl_woT,  0, 2048, 2048, 0);
    TS(ex_wo, ex_woT,  0, 2048, 1024, 0);
    TS(vl_wg, vl_wguT, 0, 2048, 6144, 1);
    TS(vl_wu, vl_wguT, 0, 2048, 6144, 2);
    TS(ex_wg, ex_wguT, 0, 1024, 3072, 1);
    TS(ex_wu, ex_wguT, 0, 1024, 3072, 2);
    TS(vl_wd, vl_wdT,  0, 6144, 2048, 0);
    TS(ex_wd, ex_wdT,  0, 3072, 1024, 0);

    // EX QKV GEMM
    TG(0, X2s, X2s + NX2, ex_wqkvT, nullptr, QKV2, (fp16*)nullptr, (fp16*)nullptr, MEX, 4096, 1024, 0);

    // head rmsnorm + RoPE -> fp16 Q (pre-scaled), K; V transpose
    qkv_post_k<<<dim3(SVL, HQ,  BB), 128>>>(QKV1,        4096, vl_qn, posids, Qh, HQ,  SVL, 0,   ATT_SCALE);
    qkv_post_k<<<dim3(SEX, HQ,  BB), 128>>>(QKV2,        4096, ex_qn, posids, Qh, HQ,  SEX, SVL, ATT_SCALE);
    qkv_post_k<<<dim3(SVL, HKV, BB), 128>>>(QKV1 + 2048, 4096, vl_kn, posids, Kh, HKV, SVL, 0,   1.0f);
    qkv_post_k<<<dim3(SEX, HKV, BB), 128>>>(QKV2 + 2048, 4096, ex_kn, posids, Kh, HKV, SEX, SVL, 1.0f);
    vtrans_k<<<dim3(SVL/32, DH/32, BB*HKV), dim3(32, 8)>>>(QKV1, 4096, Vt, SVL, 0);
    vtrans_k<<<dim3(SEX/32, DH/32, BB*HKV), dim3(32, 8)>>>(QKV2, 4096, Vt, SEX, SVL);

    // tensor-core attention (writes A splits)
    attn_k<<<dim3(SS/64, HQ, BB), 128, ATTN_SMEM>>>(Qh, Kh, Vt,
                                                    A1s, A1s + NA1, A2s, A2s + NA2);

    // output projection + residual
    TG(0, A1s, A1s + NA1, vl_woT, hs_vl, O1, (fp16*)nullptr, (fp16*)nullptr, MVL, 2048, 2048, 0);
    TG(0, A2s, A2s + NA2, ex_woT, hs_ex, O2, (fp16*)nullptr, (fp16*)nullptr, MEX, 1024, 2048, 0);

    // pre-MLP rmsnorm -> X splits
    rmsnorm_split_k<<<MVL, 256>>>(O1, vl_ln2, X1s, X1s + NX1, DVL);
    rmsnorm_split_k<<<MEX, 256>>>(O2, ex_ln2, X2s, X2s + NX2, DEX);

    // fused gate/up GEMM -> silu(g)*u -> GU splits
    TG(1, X1s, X1s + NX1, vl_wguT, nullptr, (float*)nullptr, GU1s, GU1s + NG1, MVL, 2*IVL, 2048, IVL);
    TG(1, X2s, X2s + NX2, ex_wguT, nullptr, (float*)nullptr, GU2s, GU2s + NG2, MEX, 2*IEX, 1024, IEX);

    // down projection + residual -> outputs
    TG(0, GU1s, GU1s + NG1, vl_wdT, O1, out_vl, (fp16*)nullptr, (fp16*)nullptr, MVL, 2048, 6144, 0);
    TG(0, GU2s, GU2s + NG2, ex_wdT, O2, out_ex, (fp16*)nullptr, (fp16*)nullptr, MEX, 1024, 3072, 0);
#undef TS
#undef TG
}

// round 14
// speedup vs baseline: 1.5921x; 1.5921x over previous
#include <cuda_runtime.h>
#include <cuda_fp16.h>
#include <math.h>
#include <stdint.h>

// ---------------- problem constants ----------------
#define BB   4
#define SVL  1024
#define SEX  64
#define SS   1088
#define DVL  2048
#define DEX  1024
#define HQ   16
#define HKV  8
#define DH   128
#define IVL  6144
#define IEX  3072
#define MVL  (BB*SVL)      // 4096
#define MEX  (BB*SEX)      // 256
#define EPSV 1e-6f
#define ATT_SCALE 0.08838834764831845f
#define LOG2_THETA 22.253496664211536f

typedef __half fp16;

// ---------------- low-level helpers ----------------
__device__ __forceinline__ uint32_t smem_u32(const void* p) {
    uint32_t a;
    asm("{ .reg .u64 t; cvta.to.shared.u64 t, %1; cvt.u32.u64 %0, t; }" : "=r"(a) : "l"(p));
    return a;
}
__device__ __forceinline__ void ldsm4(uint32_t* r, uint32_t addr) {
    asm volatile("ldmatrix.sync.aligned.m8n8.x4.shared.b16 {%0,%1,%2,%3}, [%4];"
                 : "=r"(r[0]), "=r"(r[1]), "=r"(r[2]), "=r"(r[3]) : "r"(addr));
}
__device__ __forceinline__ void mma_f16(float* c, const uint32_t* a, const uint32_t* b) {
    asm("mma.sync.aligned.m16n8k16.row.col.f32.f16.f16.f32 "
        "{%0,%1,%2,%3}, {%4,%5,%6,%7}, {%8,%9}, {%0,%1,%2,%3};"
        : "+f"(c[0]), "+f"(c[1]), "+f"(c[2]), "+f"(c[3])
        : "r"(a[0]), "r"(a[1]), "r"(a[2]), "r"(a[3]), "r"(b[0]), "r"(b[1]));
}
__device__ __forceinline__ void cpasync16(uint32_t dst, const void* src) {
    asm volatile("cp.async.cg.shared.global [%0], [%1], 16;" :: "r"(dst), "l"(src));
}
__device__ __forceinline__ float silu_f(float g) {
    return g / (1.f + __expf(-g));
}

// ---------------- device scratch ----------------
__device__ fp16 g_vl_wqkvT[4096u*2048u];
__device__ fp16 g_ex_wqkvT[4096u*1024u];
__device__ fp16 g_vl_woT[2048u*2048u];
__device__ fp16 g_ex_woT[1024u*2048u];
__device__ fp16 g_vl_wguT[12288u*2048u];   // 8-col interleaved g/u packing
__device__ fp16 g_ex_wguT[6144u*1024u];
__device__ fp16 g_vl_wdT[2048u*6144u];
__device__ fp16 g_ex_wdT[1024u*3072u];
// single-plane fp16 activations
__device__ fp16 g_X1[(size_t)MVL*DVL];
__device__ fp16 g_X2[(size_t)MEX*DEX];
__device__ fp16 g_A1[(size_t)MVL*(HQ*DH)];
__device__ fp16 g_A2[(size_t)MEX*(HQ*DH)];
__device__ fp16 g_GU1[(size_t)MVL*IVL];
__device__ fp16 g_GU2[(size_t)MEX*IEX];
// fp32 intermediates
__device__ float g_QKV1[(size_t)MVL*4096u];
__device__ float g_QKV2[(size_t)MEX*4096u];
__device__ float g_O1[(size_t)MVL*DVL];
__device__ float g_O2[(size_t)MEX*DEX];
// fp16 attention operands
__device__ fp16 g_Qh[(size_t)BB*HQ*SS*DH];
__device__ fp16 g_Kh[(size_t)BB*HKV*SS*DH];
__device__ fp16 g_Vt[(size_t)BB*HKV*DH*SS];

// ---------------- transpose: W[K][N] -> T[N][K] fp16, optional row map ----------
__global__ __launch_bounds__(256) void tsplit_k(const float* __restrict__ W,
                                                fp16* __restrict__ T,
                                                int K, int N, int mode)
{
    __shared__ float t[32][33];
    const int n0 = blockIdx.x * 32, k0 = blockIdx.y * 32;
    const int tx = threadIdx.x, ty = threadIdx.y;
    #pragma unroll
    for (int j = 0; j < 4; j++)
        t[ty + 8 * j][tx] = W[(size_t)(k0 + ty + 8 * j) * N + n0 + tx];
    __syncthreads();
    #pragma unroll
    for (int j = 0; j < 4; j++) {
        const int n = n0 + ty + 8 * j;
        int p = n;
        if (mode == 1) p = ((n >> 3) << 4) | (n & 7);
        else if (mode == 2) p = ((n >> 3) << 4) | 8 | (n & 7);
        T[(size_t)p * K + k0 + tx] = __float2half(t[tx][ty + 8 * j]);
    }
}

// ---------------- merged QKV weight transpose ----------------
__global__ __launch_bounds__(256) void tsplit_qkv_k(const float* __restrict__ Wq,
                                                    const float* __restrict__ Wk,
                                                    const float* __restrict__ Wv,
                                                    fp16* __restrict__ T, int K)
{
    __shared__ float t[32][33];
    const int n0 = blockIdx.x * 32, k0 = blockIdx.y * 32;
    const int tx = threadIdx.x, ty = threadIdx.y;
    const float* W; int nb, Ns;
    if (n0 < 2048)      { W = Wq; nb = n0;        Ns = 2048; }
    else if (n0 < 3072) { W = Wk; nb = n0 - 2048; Ns = 1024; }
    else                { W = Wv; nb = n0 - 3072; Ns = 1024; }
    #pragma unroll
    for (int j = 0; j < 4; j++)
        t[ty + 8 * j][tx] = W[(size_t)(k0 + ty + 8 * j) * Ns + nb + tx];
    __syncthreads();
    #pragma unroll
    for (int j = 0; j < 4; j++)
        T[(size_t)(n0 + ty + 8 * j) * K + k0 + tx] = __float2half(t[tx][ty + 8 * j]);
}

// ---------------- rmsnorm -> fp16 ----------------
__global__ __launch_bounds__(256) void rmsnorm_h_k(const float* __restrict__ x,
                                                   const float* __restrict__ w,
                                                   fp16* __restrict__ y, int D)
{
    const int row = blockIdx.x;
    const float* xr = x + (size_t)row * D;
    float s = 0.f;
    for (int i = threadIdx.x; i < D; i += 256) { float v = xr[i]; s += v * v; }
    #pragma unroll
    for (int o = 16; o; o >>= 1) s += __shfl_xor_sync(0xffffffffu, s, o);
    __shared__ float ws[8];
    if ((threadIdx.x & 31) == 0) ws[threadIdx.x >> 5] = s;
    __syncthreads();
    float tot = 0.f;
    #pragma unroll
    for (int i = 0; i < 8; i++) tot += ws[i];
    const float r = rsqrtf(tot / (float)D + EPSV);
    for (int i = threadIdx.x; i < D; i += 256)
        y[(size_t)row * D + i] = __float2half(xr[i] * r * w[i]);
}

// ---------------- head rmsnorm + RoPE -> fp16 [B,H,SS,DH] ----------------
__global__ __launch_bounds__(128) void qkv_post_k(const float* __restrict__ raw,
                                                  int rowStride,
                                                  const float* __restrict__ w,
                                                  const int* __restrict__ pos_ids,
                                                  fp16* __restrict__ out,
                                                  int H, int sCount, int seqOff,
                                                  float outScale)
{
    __shared__ float sh[DH];
    __shared__ float ws[4];
    const int d = threadIdx.x;
    const int s = blockIdx.x, h = blockIdx.y, b = blockIdx.z;
    const int row = b * sCount + s;
    float v = raw[(size_t)row * rowStride + h * DH + d];
    {
        float v2 = v * v;
        #pragma unroll
        for (int o = 16; o; o >>= 1) v2 += __shfl_xor_sync(0xffffffffu, v2, o);
        if ((d & 31) == 0) ws[d >> 5] = v2;
        __syncthreads();
        float tot = ws[0] + ws[1] + ws[2] + ws[3];
        v = v * rsqrtf(tot * (1.0f / DH) + EPSV) * w[d];
    }
    const int gs = seqOff + s;
    {
        sh[d] = v;
        __syncthreads();
        const float partner = (d < 64) ? -sh[d + 64] : sh[d - 64];
        const int pos = pos_ids[b * SS + gs];
        const float fr = (float)(d & 63) * (1.0f / 64.0f);
        const float invf = exp2f(-fr * LOG2_THETA);
        float sn, cs;
        sincosf((float)pos * invf, &sn, &cs);
        v = v * cs + partner * sn;
    }
    out[(((size_t)b * H + h) * SS + gs) * DH + d] = __float2half(v * outScale);
}

// ---------------- V transpose ----------------
__global__ __launch_bounds__(256) void vtrans_k(const float* __restrict__ qkv, int rowStride,
                                                fp16* __restrict__ Vt, int sCount, int seqOff)
{
    __shared__ float t[32][33];
    const int s0 = blockIdx.x * 32, d0 = blockIdx.y * 32, z = blockIdx.z;
    const int b = z / HKV, h = z - b * HKV;
    const int tx = threadIdx.x, ty = threadIdx.y;
    #pragma unroll
    for (int j = 0; j < 4; j++) {
        const int s = s0 + ty + 8 * j;
        t[ty + 8 * j][tx] = qkv[(size_t)(b * sCount + s) * rowStride + 3072 + h * DH + d0 + tx];
    }
    __syncthreads();
    #pragma unroll
    for (int j = 0; j < 4; j++) {
        const int d = d0 + ty + 8 * j;
        Vt[((size_t)z * DH + d) * SS + seqOff + s0 + tx] = __float2half(t[tx][ty + 8 * j]);
    }
}

// ---------------- fp16 single-term warp-MMA GEMM: C = A @ B^T (+R) --------------
// CTA 128x256, 8 warps (2x4), warp tile 64x64, KC=64, 3-stage cp.async ring.
// FUSE=1: B rows are 8-col interleaved g/u; epilogue: silu(g)*u -> fp16.
#define KC 64
#define ROWB 144
#define A_BYTES (128*ROWB)                 // 18432
#define B_BYTES (256*ROWB)                 // 36864
#define STAGE_BYTES (A_BYTES + B_BYTES)    // 55296
#define NSTAGE 3
#define GEMM_SMEM (NSTAGE*STAGE_BYTES)     // 165888

__device__ __forceinline__ void g_load_stage(uint32_t sb,
    const fp16* __restrict__ A, const fp16* __restrict__ B,
    int bm, int bn, int K, int k0, int tid)
{
    #pragma unroll
    for (int it = 0; it < 4; it++) {
        const int id = tid + it * 256;
        const int row = id >> 3, col = id & 7;
        cpasync16(sb + (uint32_t)row * ROWB + col * 16,
                  A + (size_t)(bm + row) * K + k0 + col * 8);
    }
    #pragma unroll
    for (int it = 0; it < 8; it++) {
        const int id = tid + it * 256;
        const int row = id >> 3, col = id & 7;
        cpasync16(sb + A_BYTES + (uint32_t)row * ROWB + col * 16,
                  B + (size_t)(bn + row) * K + k0 + col * 8);
    }
    asm volatile("cp.async.commit_group;" ::: "memory");
}

template<int FUSE>
__global__ __launch_bounds__(256, 1)
void mmagemm_k(const fp16* __restrict__ A, const fp16* __restrict__ B,
               const float* __restrict__ R, float* __restrict__ C,
               fp16* __restrict__ oh,
               int N, int K, int Nout)
{
    extern __shared__ char smem[];
    const uint32_t smem_base = smem_u32(smem);
    const int tid = threadIdx.x;
    const int lane = tid & 31, warp = tid >> 5;
    const int wm = warp >> 2, wn = warp & 3;           // 2 x 4 warp grid
    const int bm = blockIdx.y * 128, bn = blockIdx.x * 256;

    float acc[32][4];
    #pragma unroll
    for (int i = 0; i < 32; i++)
        #pragma unroll
        for (int j = 0; j < 4; j++) acc[i][j] = 0.f;

    const int laneRA = (lane & 7) + ((lane >> 3) & 1) * 8;
    const int laneCA = (lane >> 4) * 8;
    const int jmB = lane >> 3;
    const int laneRB = (jmB >> 1) * 8 + (lane & 7);
    const int laneCB = (jmB & 1) * 8;

    const int nst = K / KC;
    g_load_stage(smem_base, A, B, bm, bn, K, 0, tid);
    g_load_stage(smem_base + STAGE_BYTES, A, B, bm, bn, K, KC, tid);

    for (int s = 0; s < nst; s++) {
        if (s + 2 < nst)
            g_load_stage(smem_base + ((s + 2) % NSTAGE) * STAGE_BYTES,
                         A, B, bm, bn, K, (s + 2) * KC, tid);
        else
            asm volatile("cp.async.commit_group;" ::: "memory");
        asm volatile("cp.async.wait_group 2;" ::: "memory");
        __syncthreads();

        const uint32_t sb = smem_base + (s % NSTAGE) * STAGE_BYTES;
        #pragma unroll
        for (int kk = 0; kk < KC; kk += 16) {
            uint32_t bf[4][4];
            #pragma unroll
            for (int j = 0; j < 4; j++) {
                const uint32_t off = (uint32_t)(wn*64 + j*16 + laneRB) * ROWB
                                   + 2 * (laneCB + kk);
                ldsm4(bf[j], sb + A_BYTES + off);
            }
            #pragma unroll
            for (int i = 0; i < 4; i++) {
                uint32_t ah[4];
                const uint32_t offA = (uint32_t)(wm*64 + i*16 + laneRA) * ROWB
                                    + 2 * (laneCA + kk);
                ldsm4(ah, sb + offA);
                #pragma unroll
                for (int j = 0; j < 8; j++)
                    mma_f16(acc[i*8 + j], ah, &bf[j >> 1][(j & 1) * 2]);
            }
        }
        __syncthreads();
    }

    if (!FUSE) {
        #pragma unroll
        for (int i = 0; i < 4; i++) {
            const int mrow = bm + wm*64 + i*16 + (lane >> 2);
            #pragma unroll
            for (int j = 0; j < 8; j++) {
                const int ncol = bn + wn*64 + j*8 + (lane & 3)*2;
                const float* a = acc[i*8 + j];
                const size_t i0 = (size_t)mrow * N + ncol;
                const size_t i1 = (size_t)(mrow + 8) * N + ncol;
                float2 v0 = make_float2(a[0], a[1]);
                float2 v1 = make_float2(a[2], a[3]);
                if (R) {
                    float2 r0 = *(const float2*)(R + i0);
                    float2 r1 = *(const float2*)(R + i1);
                    v0.x += r0.x; v0.y += r0.y;
                    v1.x += r1.x; v1.y += r1.y;
                }
                *(float2*)(C + i0) = v0;
                *(float2*)(C + i1) = v1;
            }
        }
    } else {
        #pragma unroll
        for (int i = 0; i < 4; i++) {
            const int mrow = bm + wm*64 + i*16 + (lane >> 2);
            #pragma unroll
            for (int t = 0; t < 4; t++) {
                const float* g = acc[i*8 + 2*t];
                const float* u = acc[i*8 + 2*t + 1];
                const int ncol = (bn >> 1) + wn*32 + t*8 + (lane & 3)*2;
                const size_t i0 = (size_t)mrow * Nout + ncol;
                const size_t i1 = (size_t)(mrow + 8) * Nout + ncol;
                *(__half2*)(oh + i0) = __floats2half2_rn(silu_f(g[0]) * u[0],
                                                         silu_f(g[1]) * u[1]);
                *(__half2*)(oh + i1) = __floats2half2_rn(silu_f(g[2]) * u[2],
                                                         silu_f(g[3]) * u[3]);
            }
        }
    }
}

// ---------------- tensor-core flash attention ----------------
#define TBK 64
#define QK_ROWB 272
#define VT_ROWB 144
#define QTILE_B (64*QK_ROWB)
#define KTILE_B (64*QK_ROWB)
#define VTILE_B (128*VT_ROWB)
#define AT_STAGE (KTILE_B + VTILE_B)
#define ATTN_SMEM (QTILE_B + 2*AT_STAGE)

__device__ __forceinline__ void attn_load_stage(uint32_t sb, const fp16* __restrict__ Kb,
                                                const fp16* __restrict__ Vb, int k0, int tid)
{
    #pragma unroll
    for (int it = 0; it < 8; it++) {
        const int id = tid + it * 128;
        const int row = id >> 4, col = id & 15;
        cpasync16(sb + (uint32_t)row * QK_ROWB + col * 16,
                  Kb + (size_t)(k0 + row) * DH + col * 8);
    }
    #pragma unroll
    for (int it = 0; it < 8; it++) {
        const int id = tid + it * 128;
        const int row = id >> 3, col = id & 7;
        cpasync16(sb + KTILE_B + (uint32_t)row * VT_ROWB + col * 16,
                  Vb + (size_t)row * SS + k0 + col * 8);
    }
    asm volatile("cp.async.commit_group;" ::: "memory");
}

__global__ __launch_bounds__(128) void attn_k(const fp16* __restrict__ Qg,
                                              const fp16* __restrict__ Kg,
                                              const fp16* __restrict__ Vtg,
                                              fp16* __restrict__ a1, fp16* __restrict__ a2)
{
    extern __shared__ char smem[];
    const uint32_t sQ = smem_u32(smem);
    const int tid = threadIdx.x;
    const int lane = tid & 31, w = tid >> 5;
    const int b = blockIdx.z, h = blockIdx.y;
    const int q0 = blockIdx.x * 64;
    const int kvh = h >> 1;
    const fp16* Qb = Qg + ((size_t)(b * HQ + h) * SS + q0) * DH;
    const fp16* Kb = Kg + (size_t)(b * HKV + kvh) * SS * DH;
    const fp16* Vb = Vtg + (size_t)(b * HKV + kvh) * DH * SS;

    const int nt = (q0 < SVL) ? (SVL / TBK) : (SS / TBK);

    #pragma unroll
    for (int it = 0; it < 8; it++) {
        const int id = tid + it * 128;
        const int row = id >> 4, col = id & 15;
        cpasync16(sQ + (uint32_t)row * QK_ROWB + col * 16, Qb + (size_t)row * DH + col * 8);
    }
    attn_load_stage(sQ + QTILE_B, Kb, Vb, 0, tid);

    const int laneRA = (lane & 7) + ((lane >> 3) & 1) * 8;
    const int laneCA = (lane >> 4) * 8;
    const int jmB = lane >> 3;
    const int laneRB = (jmB >> 1) * 8 + (lane & 7);
    const int laneCB = (jmB & 1) * 8;

    float o[16][4];
    #pragma unroll
    for (int n = 0; n < 16; n++)
        #pragma unroll
        for (int j = 0; j < 4; j++) o[n][j] = 0.f;
    float m0 = -1e30f, m1 = -1e30f, l0 = 0.f, l1 = 0.f;

    int buf = 0;
    for (int t = 0; t < nt; t++) {
        if (t + 1 < nt) {
            attn_load_stage(sQ + QTILE_B + (buf ^ 1) * AT_STAGE, Kb, Vb, (t + 1) * TBK, tid);
            asm volatile("cp.async.wait_group 1;" ::: "memory");
        } else {
            asm volatile("cp.async.wait_group 0;" ::: "memory");
        }
        __syncthreads();

        const uint32_t sK = sQ + QTILE_B + buf * AT_STAGE;
        const uint32_t sV = sK + KTILE_B;
        const int k0 = t * TBK;

        float s[8][4];
        #pragma unroll
        for (int j = 0; j < 8; j++) { s[j][0]=0.f; s[j][1]=0.f; s[j][2]=0.f; s[j][3]=0.f; }
        #pragma unroll
        for (int kk = 0; kk < 8; kk++) {
            uint32_t qa[4];
            ldsm4(qa, sQ + (uint32_t)(w*16 + laneRA) * QK_ROWB + 2 * (laneCA + kk*16));
            #pragma unroll
            for (int jj = 0; jj < 4; jj++) {
                uint32_t kb[4];
                ldsm4(kb, sK + (uint32_t)(jj*16 + laneRB) * QK_ROWB + 2 * (laneCB + kk*16));
                mma_f16(s[2*jj],   qa, &kb[0]);
                mma_f16(s[2*jj+1], qa, &kb[2]);
            }
        }

        if (k0 >= SVL) {
            const int qr0 = q0 + w*16 + (lane >> 2);
            #pragma unroll
            for (int j = 0; j < 8; j++) {
                const int kc = k0 + j*8 + 2*(lane & 3);
                if (kc   > qr0)     s[j][0] = -1e9f;
                if (kc+1 > qr0)     s[j][1] = -1e9f;
                if (kc   > qr0 + 8) s[j][2] = -1e9f;
                if (kc+1 > qr0 + 8) s[j][3] = -1e9f;
            }
        }

        float mx0 = m0, mx1 = m1;
        #pragma unroll
        for (int j = 0; j < 8; j++) {
            mx0 = fmaxf(mx0, fmaxf(s[j][0], s[j][1]));
            mx1 = fmaxf(mx1, fmaxf(s[j][2], s[j][3]));
        }
        mx0 = fmaxf(mx0, __shfl_xor_sync(0xffffffffu, mx0, 1));
        mx0 = fmaxf(mx0, __shfl_xor_sync(0xffffffffu, mx0, 2));
        mx1 = fmaxf(mx1, __shfl_xor_sync(0xffffffffu, mx1, 1));
        mx1 = fmaxf(mx1, __shfl_xor_sync(0xffffffffu, mx1, 2));
        const float corr0 = __expf(m0 - mx0), corr1 = __expf(m1 - mx1);
        m0 = mx0; m1 = mx1;
        l0 *= corr0; l1 *= corr1;
        #pragma unroll
        for (int n = 0; n < 16; n++) {
            o[n][0] *= corr0; o[n][1] *= corr0;
            o[n][2] *= corr1; o[n][3] *= corr1;
        }

        uint32_t pf[4][4];
        #pragma unroll
        for (int j = 0; j < 8; j++) {
            const float p0 = __expf(s[j][0] - mx0);
            const float p1 = __expf(s[j][1] - mx0);
            const float p2 = __expf(s[j][2] - mx1);
            const float p3 = __expf(s[j][3] - mx1);
            l0 += p0 + p1; l1 += p2 + p3;
            __half2 ha = __floats2half2_rn(p0, p1);
            __half2 hb = __floats2half2_rn(p2, p3);
            const int tt = j >> 1, o2 = (j & 1) * 2;
            pf[tt][o2]     = *(uint32_t*)&ha;
            pf[tt][o2 + 1] = *(uint32_t*)&hb;
        }

        #pragma unroll
        for (int tt = 0; tt < 4; tt++) {
            #pragma unroll
            for (int jj = 0; jj < 8; jj++) {
                uint32_t vb[4];
                ldsm4(vb, sV + (uint32_t)(jj*16 + laneRB) * VT_ROWB + 2 * (laneCB + tt*16));
                mma_f16(o[2*jj],   pf[tt], &vb[0]);
                mma_f16(o[2*jj+1], pf[tt], &vb[2]);
            }
        }
        __syncthreads();
        buf ^= 1;
    }

    l0 += __shfl_xor_sync(0xffffffffu, l0, 1);
    l0 += __shfl_xor_sync(0xffffffffu, l0, 2);
    l1 += __shfl_xor_sync(0xffffffffu, l1, 1);
    l1 += __shfl_xor_sync(0xffffffffu, l1, 2);
    const float li0 = 1.f / l0, li1 = 1.f / l1;
    const int qr0 = q0 + w*16 + (lane >> 2);
    #pragma unroll
    for (int n = 0; n < 16; n++) {
        const int col = h * DH + n*8 + 2*(lane & 3);
        #pragma unroll
        for (int half = 0; half < 2; half++) {
            const int qr = qr0 + half * 8;
            const float va = o[n][half*2]     * (half ? li1 : li0);
            const float vb2 = o[n][half*2 + 1] * (half ? li1 : li0);
            size_t idx;
            fp16* op;
            if (qr < SVL) { idx = (size_t)(b * SVL + qr) * (HQ*DH) + col; op = a1; }
            else          { idx = (size_t)(b * SEX + qr - SVL) * (HQ*DH) + col; op = a2; }
            *(__half2*)(op + idx) = __floats2half2_rn(va, vb2);
        }
    }
}

// ---------------- launch ----------------
extern "C" void kernel_launch(void* const* d_in, const int* in_sizes, int n_in,
                              void* d_out, int out_size)
{
    (void)in_sizes; (void)n_in; (void)out_size;
    const float* hs_vl  = (const float*)d_in[0];
    const float* hs_ex  = (const float*)d_in[1];
    const int*   posids = (const int*)  d_in[2];
    const float* vl_ln1 = (const float*)d_in[4];
    const float* vl_wq  = (const float*)d_in[5];
    const float* vl_wk  = (const float*)d_in[6];
    const float* vl_wv  = (const float*)d_in[7];
    const float* vl_qn  = (const float*)d_in[8];
    const float* vl_kn  = (const float*)d_in[9];
    const float* vl_wo  = (const float*)d_in[10];
    const float* vl_ln2 = (const float*)d_in[11];
    const float* vl_wg  = (const float*)d_in[12];
    const float* vl_wu  = (const float*)d_in[13];
    const float* vl_wd  = (const float*)d_in[14];
    const float* ex_ln1 = (const float*)d_in[15];
    const float* ex_wq  = (const float*)d_in[16];
    const float* ex_wk  = (const float*)d_in[17];
    const float* ex_wv  = (const float*)d_in[18];
    const float* ex_qn  = (const float*)d_in[19];
    const float* ex_kn  = (const float*)d_in[20];
    const float* ex_wo  = (const float*)d_in[21];
    const float* ex_ln2 = (const float*)d_in[22];
    const float* ex_wg  = (const float*)d_in[23];
    const float* ex_wu  = (const float*)d_in[24];
    const float* ex_wd  = (const float*)d_in[25];

    float* out_vl = (float*)d_out;
    float* out_ex = out_vl + (size_t)MVL * DVL;

#define SYM(T, p, s) T* p; cudaGetSymbolAddress((void**)&p, s)
    SYM(fp16, vl_wqkvT, g_vl_wqkvT); SYM(fp16, ex_wqkvT, g_ex_wqkvT);
    SYM(fp16, vl_woT, g_vl_woT);     SYM(fp16, ex_woT, g_ex_woT);
    SYM(fp16, vl_wguT, g_vl_wguT);   SYM(fp16, ex_wguT, g_ex_wguT);
    SYM(fp16, vl_wdT, g_vl_wdT);     SYM(fp16, ex_wdT, g_ex_wdT);
    SYM(fp16, X1, g_X1); SYM(fp16, X2, g_X2);
    SYM(fp16, A1, g_A1); SYM(fp16, A2, g_A2);
    SYM(fp16, GU1, g_GU1); SYM(fp16, GU2, g_GU2);
    SYM(float, QKV1, g_QKV1); SYM(float, QKV2, g_QKV2);
    SYM(fp16, Qh, g_Qh); SYM(fp16, Kh, g_Kh); SYM(fp16, Vt, g_Vt);
    SYM(float, O1, g_O1); SYM(float, O2, g_O2);
#undef SYM

    cudaFuncSetAttribute(mmagemm_k<0>, cudaFuncAttributeMaxDynamicSharedMemorySize, GEMM_SMEM);
    cudaFuncSetAttribute(mmagemm_k<1>, cudaFuncAttributeMaxDynamicSharedMemorySize, GEMM_SMEM);
    cudaFuncSetAttribute(attn_k, cudaFuncAttributeMaxDynamicSharedMemorySize, ATTN_SMEM);

#define TS(W, T, ROFF, KK, NN, MODE) \
    tsplit_k<<<dim3((NN)/32, (KK)/32), dim3(32, 8)>>>(W, (T) + (size_t)(ROFF)*(KK), KK, NN, MODE)
#define TG(FUSE, AA, BT, Rr, Cc, OH, M, N, K, NOUT) \
    mmagemm_k<FUSE><<<dim3((N)/256, (M)/128), 256, GEMM_SMEM>>>( \
        AA, BT, Rr, Cc, OH, N, K, NOUT)

    // launches 0-2: deps of the big GEMM; launch 3 = VL QKV GEMM (ncu captures idx 3)
    tsplit_qkv_k<<<dim3(4096/32, 2048/32), dim3(32, 8)>>>(vl_wq, vl_wk, vl_wv, vl_wqkvT, 2048);
    rmsnorm_h_k<<<MVL, 256>>>(hs_vl, vl_ln1, X1, DVL);
    rmsnorm_h_k<<<MEX, 256>>>(hs_ex, ex_ln1, X2, DEX);
    TG(0, X1, vl_wqkvT, nullptr, QKV1, (fp16*)nullptr, MVL, 4096, 2048, 0);

    // remaining weight transforms
    tsplit_qkv_k<<<dim3(4096/32, 1024/32), dim3(32, 8)>>>(ex_wq, ex_wk, ex_wv, ex_wqkvT, 1024);
    TS(vl_wo, vl_woT,  0, 2048, 2048, 0);
    TS(ex_wo, ex_woT,  0, 2048, 1024, 0);
    TS(vl_wg, vl_wguT, 0, 2048, 6144, 1);
    TS(vl_wu, vl_wguT, 0, 2048, 6144, 2);
    TS(ex_wg, ex_wguT, 0, 1024, 3072, 1);
    TS(ex_wu, ex_wguT, 0, 1024, 3072, 2);
    TS(vl_wd, vl_wdT,  0, 6144, 2048, 0);
    TS(ex_wd, ex_wdT,  0, 3072, 1024, 0);

    // EX QKV GEMM
    TG(0, X2, ex_wqkvT, nullptr, QKV2, (fp16*)nullptr, MEX, 4096, 1024, 0);

    // head rmsnorm + RoPE -> fp16 Q (pre-scaled), K; V transpose
    qkv_post_k<<<dim3(SVL, HQ,  BB), 128>>>(QKV1,        4096, vl_qn, posids, Qh, HQ,  SVL, 0,   ATT_SCALE);
    qkv_post_k<<<dim3(SEX, HQ,  BB), 128>>>(QKV2,        4096, ex_qn, posids, Qh, HQ,  SEX, SVL, ATT_SCALE);
    qkv_post_k<<<dim3(SVL, HKV, BB), 128>>>(QKV1 + 2048, 4096, vl_kn, posids, Kh, HKV, SVL, 0,   1.0f);
    qkv_post_k<<<dim3(SEX, HKV, BB), 128>>>(QKV2 + 2048, 4096, ex_kn, posids, Kh, HKV, SEX, SVL, 1.0f);
    vtrans_k<<<dim3(SVL/32, DH/32, BB*HKV), dim3(32, 8)>>>(QKV1, 4096, Vt, SVL, 0);
    vtrans_k<<<dim3(SEX/32, DH/32, BB*HKV), dim3(32, 8)>>>(QKV2, 4096, Vt, SEX, SVL);

    // tensor-core attention
    attn_k<<<dim3(SS/64, HQ, BB), 128, ATTN_SMEM>>>(Qh, Kh, Vt, A1, A2);

    // output projection + residual
    TG(0, A1, vl_woT, hs_vl, O1, (fp16*)nullptr, MVL, 2048, 2048, 0);
    TG(0, A2, ex_woT, hs_ex, O2, (fp16*)nullptr, MEX, 1024, 2048, 0);

    // pre-MLP rmsnorm
    rmsnorm_h_k<<<MVL, 256>>>(O1, vl_ln2, X1, DVL);
    rmsnorm_h_k<<<MEX, 256>>>(O2, ex_ln2, X2, DEX);

    // fused gate/up GEMM -> silu(g)*u -> GU
    TG(1, X1, vl_wguT, nullptr, (float*)nullptr, GU1, MVL, 2*IVL, 2048, IVL);
    TG(1, X2, ex_wguT, nullptr, (float*)nullptr, GU2, MEX, 2*IEX, 1024, IEX);

    // down projection + residual -> outputs
    TG(0, GU1, vl_wdT, O1, out_vl, (fp16*)nullptr, MVL, 2048, 6144, 0);
    TG(0, GU2, ex_wdT, O2, out_ex, (fp16*)nullptr, MEX, 1024, 3072, 0);
#undef TS
#undef TG
}

// round 15
// speedup vs baseline: 1.7558x; 1.1028x over previous
#include <cuda_runtime.h>
#include <cuda_fp16.h>
#include <math.h>
#include <stdint.h>

// ---------------- problem constants ----------------
#define BB   4
#define SVL  1024
#define SEX  64
#define SS   1088
#define DVL  2048
#define DEX  1024
#define HQ   16
#define HKV  8
#define DH   128
#define IVL  6144
#define IEX  3072
#define MVL  (BB*SVL)      // 4096
#define MEX  (BB*SEX)      // 256
#define EPSV 1e-6f
#define ATT_SCALE 0.08838834764831845f
#define LOG2_THETA 22.253496664211536f

typedef __half fp16;

// ---------------- low-level helpers ----------------
__device__ __forceinline__ uint32_t smem_u32(const void* p) {
    uint32_t a;
    asm("{ .reg .u64 t; cvta.to.shared.u64 t, %1; cvt.u32.u64 %0, t; }" : "=r"(a) : "l"(p));
    return a;
}
__device__ __forceinline__ void ldsm4(uint32_t* r, uint32_t addr) {
    asm volatile("ldmatrix.sync.aligned.m8n8.x4.shared.b16 {%0,%1,%2,%3}, [%4];"
                 : "=r"(r[0]), "=r"(r[1]), "=r"(r[2]), "=r"(r[3]) : "r"(addr));
}
__device__ __forceinline__ void mma_f16(float* c, const uint32_t* a, const uint32_t* b) {
    asm("mma.sync.aligned.m16n8k16.row.col.f32.f16.f16.f32 "
        "{%0,%1,%2,%3}, {%4,%5,%6,%7}, {%8,%9}, {%0,%1,%2,%3};"
        : "+f"(c[0]), "+f"(c[1]), "+f"(c[2]), "+f"(c[3])
        : "r"(a[0]), "r"(a[1]), "r"(a[2]), "r"(a[3]), "r"(b[0]), "r"(b[1]));
}
__device__ __forceinline__ void cpasync16(uint32_t dst, const void* src) {
    asm volatile("cp.async.cg.shared.global [%0], [%1], 16;" :: "r"(dst), "l"(src));
}
__device__ __forceinline__ float silu_f(float g) {
    return g / (1.f + __expf(-g));
}

// ---------------- device scratch ----------------
__device__ fp16 g_vl_wqkvT[4096u*2048u];
__device__ fp16 g_ex_wqkvT[4096u*1024u];
__device__ fp16 g_vl_woT[2048u*2048u];
__device__ fp16 g_ex_woT[1024u*2048u];
__device__ fp16 g_vl_wguT[12288u*2048u];   // 8-col interleaved g/u packing
__device__ fp16 g_ex_wguT[6144u*1024u];
__device__ fp16 g_vl_wdT[2048u*6144u];
__device__ fp16 g_ex_wdT[1024u*3072u];
__device__ fp16 g_X1[(size_t)MVL*DVL];
__device__ fp16 g_X2[(size_t)MEX*DEX];
__device__ fp16 g_A1[(size_t)MVL*(HQ*DH)];
__device__ fp16 g_A2[(size_t)MEX*(HQ*DH)];
__device__ fp16 g_GU1[(size_t)MVL*IVL];
__device__ fp16 g_GU2[(size_t)MEX*IEX];
__device__ float g_QKV1[(size_t)MVL*4096u];
__device__ float g_QKV2[(size_t)MEX*4096u];
__device__ float g_O1[(size_t)MVL*DVL];
__device__ float g_O2[(size_t)MEX*DEX];
__device__ fp16 g_Qh[(size_t)BB*HQ*SS*DH];
__device__ fp16 g_Kh[(size_t)BB*HKV*SS*DH];
__device__ fp16 g_Vt[(size_t)BB*HKV*DH*SS];

// ---------------- transpose: W[K][N] -> T[N][K] fp16, optional row map ----------
__global__ __launch_bounds__(256) void tsplit_k(const float* __restrict__ W,
                                                fp16* __restrict__ T,
                                                int K, int N, int mode)
{
    __shared__ float t[32][33];
    const int n0 = blockIdx.x * 32, k0 = blockIdx.y * 32;
    const int tx = threadIdx.x, ty = threadIdx.y;
    #pragma unroll
    for (int j = 0; j < 4; j++)
        t[ty + 8 * j][tx] = W[(size_t)(k0 + ty + 8 * j) * N + n0 + tx];
    __syncthreads();
    #pragma unroll
    for (int j = 0; j < 4; j++) {
        const int n = n0 + ty + 8 * j;
        int p = n;
        if (mode == 1) p = ((n >> 3) << 4) | (n & 7);
        else if (mode == 2) p = ((n >> 3) << 4) | 8 | (n & 7);
        T[(size_t)p * K + k0 + tx] = __float2half(t[tx][ty + 8 * j]);
    }
}

// ---------------- merged QKV weight transpose ----------------
__global__ __launch_bounds__(256) void tsplit_qkv_k(const float* __restrict__ Wq,
                                                    const float* __restrict__ Wk,
                                                    const float* __restrict__ Wv,
                                                    fp16* __restrict__ T, int K)
{
    __shared__ float t[32][33];
    const int n0 = blockIdx.x * 32, k0 = blockIdx.y * 32;
    const int tx = threadIdx.x, ty = threadIdx.y;
    const float* W; int nb, Ns;
    if (n0 < 2048)      { W = Wq; nb = n0;        Ns = 2048; }
    else if (n0 < 3072) { W = Wk; nb = n0 - 2048; Ns = 1024; }
    else                { W = Wv; nb = n0 - 3072; Ns = 1024; }
    #pragma unroll
    for (int j = 0; j < 4; j++)
        t[ty + 8 * j][tx] = W[(size_t)(k0 + ty + 8 * j) * Ns + nb + tx];
    __syncthreads();
    #pragma unroll
    for (int j = 0; j < 4; j++)
        T[(size_t)(n0 + ty + 8 * j) * K + k0 + tx] = __float2half(t[tx][ty + 8 * j]);
}

// ---------------- rmsnorm -> fp16 ----------------
__global__ __launch_bounds__(256) void rmsnorm_h_k(const float* __restrict__ x,
                                                   const float* __restrict__ w,
                                                   fp16* __restrict__ y, int D)
{
    const int row = blockIdx.x;
    const float* xr = x + (size_t)row * D;
    float s = 0.f;
    for (int i = threadIdx.x; i < D; i += 256) { float v = xr[i]; s += v * v; }
    #pragma unroll
    for (int o = 16; o; o >>= 1) s += __shfl_xor_sync(0xffffffffu, s, o);
    __shared__ float ws[8];
    if ((threadIdx.x & 31) == 0) ws[threadIdx.x >> 5] = s;
    __syncthreads();
    float tot = 0.f;
    #pragma unroll
    for (int i = 0; i < 8; i++) tot += ws[i];
    const float r = rsqrtf(tot / (float)D + EPSV);
    for (int i = threadIdx.x; i < D; i += 256)
        y[(size_t)row * D + i] = __float2half(xr[i] * r * w[i]);
}

// ---------------- head rmsnorm + RoPE -> fp16 [B,H,SS,DH] ----------------
__global__ __launch_bounds__(128) void qkv_post_k(const float* __restrict__ raw,
                                                  int rowStride,
                                                  const float* __restrict__ w,
                                                  const int* __restrict__ pos_ids,
                                                  fp16* __restrict__ out,
                                                  int H, int sCount, int seqOff,
                                                  float outScale)
{
    __shared__ float sh[DH];
    __shared__ float ws[4];
    const int d = threadIdx.x;
    const int s = blockIdx.x, h = blockIdx.y, b = blockIdx.z;
    const int row = b * sCount + s;
    float v = raw[(size_t)row * rowStride + h * DH + d];
    {
        float v2 = v * v;
        #pragma unroll
        for (int o = 16; o; o >>= 1) v2 += __shfl_xor_sync(0xffffffffu, v2, o);
        if ((d & 31) == 0) ws[d >> 5] = v2;
        __syncthreads();
        float tot = ws[0] + ws[1] + ws[2] + ws[3];
        v = v * rsqrtf(tot * (1.0f / DH) + EPSV) * w[d];
    }
    const int gs = seqOff + s;
    {
        sh[d] = v;
        __syncthreads();
        const float partner = (d < 64) ? -sh[d + 64] : sh[d - 64];
        const int pos = pos_ids[b * SS + gs];
        const float fr = (float)(d & 63) * (1.0f / 64.0f);
        const float invf = exp2f(-fr * LOG2_THETA);
        float sn, cs;
        sincosf((float)pos * invf, &sn, &cs);
        v = v * cs + partner * sn;
    }
    out[(((size_t)b * H + h) * SS + gs) * DH + d] = __float2half(v * outScale);
}

// ---------------- V transpose ----------------
__global__ __launch_bounds__(256) void vtrans_k(const float* __restrict__ qkv, int rowStride,
                                                fp16* __restrict__ Vt, int sCount, int seqOff)
{
    __shared__ float t[32][33];
    const int s0 = blockIdx.x * 32, d0 = blockIdx.y * 32, z = blockIdx.z;
    const int b = z / HKV, h = z - b * HKV;
    const int tx = threadIdx.x, ty = threadIdx.y;
    #pragma unroll
    for (int j = 0; j < 4; j++) {
        const int s = s0 + ty + 8 * j;
        t[ty + 8 * j][tx] = qkv[(size_t)(b * sCount + s) * rowStride + 3072 + h * DH + d0 + tx];
    }
    __syncthreads();
    #pragma unroll
    for (int j = 0; j < 4; j++) {
        const int d = d0 + ty + 8 * j;
        Vt[((size_t)z * DH + d) * SS + seqOff + s0 + tx] = __float2half(t[tx][ty + 8 * j]);
    }
}

// ---------------- fp16 warp-MMA GEMM: C = A @ B^T (+R) --------------------------
// CTA 128x128, 128 threads (4 warps 2x2), warp tile 64x64, KC=64, 3-stage ring.
// 2 CTAs resident per SM (independent barriers fill sync bubbles).
// FUSE=1: B rows are 8-col interleaved g/u; epilogue: silu(g)*u -> fp16.
#define KC 64
#define ROWB 144
#define A_BYTES (128*ROWB)                 // 18432
#define B_BYTES (128*ROWB)                 // 18432
#define STAGE_BYTES (A_BYTES + B_BYTES)    // 36864
#define NSTAGE 3
#define GEMM_SMEM (NSTAGE*STAGE_BYTES)     // 110592 (x2 CTAs = 221184)

__device__ __forceinline__ void g_load_stage(uint32_t sb,
    const fp16* __restrict__ A, const fp16* __restrict__ B,
    int bm, int bn, int K, int k0, int tid)
{
    #pragma unroll
    for (int it = 0; it < 8; it++) {
        const int id = tid + it * 128;
        const int row = id >> 3, col = id & 7;
        cpasync16(sb + (uint32_t)row * ROWB + col * 16,
                  A + (size_t)(bm + row) * K + k0 + col * 8);
    }
    #pragma unroll
    for (int it = 0; it < 8; it++) {
        const int id = tid + it * 128;
        const int row = id >> 3, col = id & 7;
        cpasync16(sb + A_BYTES + (uint32_t)row * ROWB + col * 16,
                  B + (size_t)(bn + row) * K + k0 + col * 8);
    }
    asm volatile("cp.async.commit_group;" ::: "memory");
}

template<int FUSE>
__global__ __launch_bounds__(128, 2)
void mmagemm_k(const fp16* __restrict__ A, const fp16* __restrict__ B,
               const float* __restrict__ R, float* __restrict__ C,
               fp16* __restrict__ oh,
               int N, int K, int Nout)
{
    extern __shared__ char smem[];
    const uint32_t smem_base = smem_u32(smem);
    const int tid = threadIdx.x;
    const int lane = tid & 31, warp = tid >> 5;
    const int wm = warp >> 1, wn = warp & 1;           // 2 x 2 warp grid
    const int bm = blockIdx.y * 128, bn = blockIdx.x * 128;

    float acc[32][4];
    #pragma unroll
    for (int i = 0; i < 32; i++)
        #pragma unroll
        for (int j = 0; j < 4; j++) acc[i][j] = 0.f;

    const int laneRA = (lane & 7) + ((lane >> 3) & 1) * 8;
    const int laneCA = (lane >> 4) * 8;
    const int jmB = lane >> 3;
    const int laneRB = (jmB >> 1) * 8 + (lane & 7);
    const int laneCB = (jmB & 1) * 8;

    const int nst = K / KC;
    g_load_stage(smem_base, A, B, bm, bn, K, 0, tid);
    g_load_stage(smem_base + STAGE_BYTES, A, B, bm, bn, K, KC, tid);

    for (int s = 0; s < nst; s++) {
        if (s + 2 < nst)
            g_load_stage(smem_base + ((s + 2) % NSTAGE) * STAGE_BYTES,
                         A, B, bm, bn, K, (s + 2) * KC, tid);
        else
            asm volatile("cp.async.commit_group;" ::: "memory");
        asm volatile("cp.async.wait_group 2;" ::: "memory");
        __syncthreads();

        const uint32_t sb = smem_base + (s % NSTAGE) * STAGE_BYTES;
        #pragma unroll
        for (int kk = 0; kk < KC; kk += 16) {
            uint32_t bf[4][4];
            #pragma unroll
            for (int j = 0; j < 4; j++) {
                const uint32_t off = (uint32_t)(wn*64 + j*16 + laneRB) * ROWB
                                   + 2 * (laneCB + kk);
                ldsm4(bf[j], sb + A_BYTES + off);
            }
            #pragma unroll
            for (int i = 0; i < 4; i++) {
                uint32_t ah[4];
                const uint32_t offA = (uint32_t)(wm*64 + i*16 + laneRA) * ROWB
                                    + 2 * (laneCA + kk);
                ldsm4(ah, sb + offA);
                #pragma unroll
                for (int j = 0; j < 8; j++)
                    mma_f16(acc[i*8 + j], ah, &bf[j >> 1][(j & 1) * 2]);
            }
        }
        __syncthreads();
    }

    if (!FUSE) {
        #pragma unroll
        for (int i = 0; i < 4; i++) {
            const int mrow = bm + wm*64 + i*16 + (lane >> 2);
            #pragma unroll
            for (int j = 0; j < 8; j++) {
                const int ncol = bn + wn*64 + j*8 + (lane & 3)*2;
                const float* a = acc[i*8 + j];
                const size_t i0 = (size_t)mrow * N + ncol;
                const size_t i1 = (size_t)(mrow + 8) * N + ncol;
                float2 v0 = make_float2(a[0], a[1]);
                float2 v1 = make_float2(a[2], a[3]);
                if (R) {
                    float2 r0 = *(const float2*)(R + i0);
                    float2 r1 = *(const float2*)(R + i1);
                    v0.x += r0.x; v0.y += r0.y;
                    v1.x += r1.x; v1.y += r1.y;
                }
                *(float2*)(C + i0) = v0;
                *(float2*)(C + i1) = v1;
            }
        }
    } else {
        #pragma unroll
        for (int i = 0; i < 4; i++) {
            const int mrow = bm + wm*64 + i*16 + (lane >> 2);
            #pragma unroll
            for (int t = 0; t < 4; t++) {
                const float* g = acc[i*8 + 2*t];
                const float* u = acc[i*8 + 2*t + 1];
                const int ncol = (bn >> 1) + wn*32 + t*8 + (lane & 3)*2;
                const size_t i0 = (size_t)mrow * Nout + ncol;
                const size_t i1 = (size_t)(mrow + 8) * Nout + ncol;
                *(__half2*)(oh + i0) = __floats2half2_rn(silu_f(g[0]) * u[0],
                                                         silu_f(g[1]) * u[1]);
                *(__half2*)(oh + i1) = __floats2half2_rn(silu_f(g[2]) * u[2],
                                                         silu_f(g[3]) * u[3]);
            }
        }
    }
}

// ---------------- tensor-core flash attention ----------------
#define TBK 64
#define QK_ROWB 272
#define VT_ROWB 144
#define QTILE_B (64*QK_ROWB)
#define KTILE_B (64*QK_ROWB)
#define VTILE_B (128*VT_ROWB)
#define AT_STAGE (KTILE_B + VTILE_B)
#define ATTN_SMEM (QTILE_B + 2*AT_STAGE)

__device__ __forceinline__ void attn_load_stage(uint32_t sb, const fp16* __restrict__ Kb,
                                                const fp16* __restrict__ Vb, int k0, int tid)
{
    #pragma unroll
    for (int it = 0; it < 8; it++) {
        const int id = tid + it * 128;
        const int row = id >> 4, col = id & 15;
        cpasync16(sb + (uint32_t)row * QK_ROWB + col * 16,
                  Kb + (size_t)(k0 + row) * DH + col * 8);
    }
    #pragma unroll
    for (int it = 0; it < 8; it++) {
        const int id = tid + it * 128;
        const int row = id >> 3, col = id & 7;
        cpasync16(sb + KTILE_B + (uint32_t)row * VT_ROWB + col * 16,
                  Vb + (size_t)row * SS + k0 + col * 8);
    }
    asm volatile("cp.async.commit_group;" ::: "memory");
}

__global__ __launch_bounds__(128) void attn_k(const fp16* __restrict__ Qg,
                                              const fp16* __restrict__ Kg,
                                              const fp16* __restrict__ Vtg,
                                              fp16* __restrict__ a1, fp16* __restrict__ a2)
{
    extern __shared__ char smem[];
    const uint32_t sQ = smem_u32(smem);
    const int tid = threadIdx.x;
    const int lane = tid & 31, w = tid >> 5;
    const int b = blockIdx.z, h = blockIdx.y;
    const int q0 = blockIdx.x * 64;
    const int kvh = h >> 1;
    const fp16* Qb = Qg + ((size_t)(b * HQ + h) * SS + q0) * DH;
    const fp16* Kb = Kg + (size_t)(b * HKV + kvh) * SS * DH;
    const fp16* Vb = Vtg + (size_t)(b * HKV + kvh) * DH * SS;

    const int nt = (q0 < SVL) ? (SVL / TBK) : (SS / TBK);

    #pragma unroll
    for (int it = 0; it < 8; it++) {
        const int id = tid + it * 128;
        const int row = id >> 4, col = id & 15;
        cpasync16(sQ + (uint32_t)row * QK_ROWB + col * 16, Qb + (size_t)row * DH + col * 8);
    }
    attn_load_stage(sQ + QTILE_B, Kb, Vb, 0, tid);

    const int laneRA = (lane & 7) + ((lane >> 3) & 1) * 8;
    const int laneCA = (lane >> 4) * 8;
    const int jmB = lane >> 3;
    const int laneRB = (jmB >> 1) * 8 + (lane & 7);
    const int laneCB = (jmB & 1) * 8;

    float o[16][4];
    #pragma unroll
    for (int n = 0; n < 16; n++)
        #pragma unroll
        for (int j = 0; j < 4; j++) o[n][j] = 0.f;
    float m0 = -1e30f, m1 = -1e30f, l0 = 0.f, l1 = 0.f;

    int buf = 0;
    for (int t = 0; t < nt; t++) {
        if (t + 1 < nt) {
            attn_load_stage(sQ + QTILE_B + (buf ^ 1) * AT_STAGE, Kb, Vb, (t + 1) * TBK, tid);
            asm volatile("cp.async.wait_group 1;" ::: "memory");
        } else {
            asm volatile("cp.async.wait_group 0;" ::: "memory");
        }
        __syncthreads();

        const uint32_t sK = sQ + QTILE_B + buf * AT_STAGE;
        const uint32_t sV = sK + KTILE_B;
        const int k0 = t * TBK;

        float s[8][4];
        #pragma unroll
        for (int j = 0; j < 8; j++) { s[j][0]=0.f; s[j][1]=0.f; s[j][2]=0.f; s[j][3]=0.f; }
        #pragma unroll
        for (int kk = 0; kk < 8; kk++) {
            uint32_t qa[4];
            ldsm4(qa, sQ + (uint32_t)(w*16 + laneRA) * QK_ROWB + 2 * (laneCA + kk*16));
            #pragma unroll
            for (int jj = 0; jj < 4; jj++) {
                uint32_t kb[4];
                ldsm4(kb, sK + (uint32_t)(jj*16 + laneRB) * QK_ROWB + 2 * (laneCB + kk*16));
                mma_f16(s[2*jj],   qa, &kb[0]);
                mma_f16(s[2*jj+1], qa, &kb[2]);
            }
        }

        if (k0 >= SVL) {
            const int qr0 = q0 + w*16 + (lane >> 2);
            #pragma unroll
            for (int j = 0; j < 8; j++) {
                const int kc = k0 + j*8 + 2*(lane & 3);
                if (kc   > qr0)     s[j][0] = -1e9f;
                if (kc+1 > qr0)     s[j][1] = -1e9f;
                if (kc   > qr0 + 8) s[j][2] = -1e9f;
                if (kc+1 > qr0 + 8) s[j][3] = -1e9f;
            }
        }

        float mx0 = m0, mx1 = m1;
        #pragma unroll
        for (int j = 0; j < 8; j++) {
            mx0 = fmaxf(mx0, fmaxf(s[j][0], s[j][1]));
            mx1 = fmaxf(mx1, fmaxf(s[j][2], s[j][3]));
        }
        mx0 = fmaxf(mx0, __shfl_xor_sync(0xffffffffu, mx0, 1));
        mx0 = fmaxf(mx0, __shfl_xor_sync(0xffffffffu, mx0, 2));
        mx1 = fmaxf(mx1, __shfl_xor_sync(0xffffffffu, mx1, 1));
        mx1 = fmaxf(mx1, __shfl_xor_sync(0xffffffffu, mx1, 2));
        const float corr0 = __expf(m0 - mx0), corr1 = __expf(m1 - mx1);
        m0 = mx0; m1 = mx1;
        l0 *= corr0; l1 *= corr1;
        #pragma unroll
        for (int n = 0; n < 16; n++) {
            o[n][0] *= corr0; o[n][1] *= corr0;
            o[n][2] *= corr1; o[n][3] *= corr1;
        }

        uint32_t pf[4][4];
        #pragma unroll
        for (int j = 0; j < 8; j++) {
            const float p0 = __expf(s[j][0] - mx0);
            const float p1 = __expf(s[j][1] - mx0);
            const float p2 = __expf(s[j][2] - mx1);
            const float p3 = __expf(s[j][3] - mx1);
            l0 += p0 + p1; l1 += p2 + p3;
            __half2 ha = __floats2half2_rn(p0, p1);
            __half2 hb = __floats2half2_rn(p2, p3);
            const int tt = j >> 1, o2 = (j & 1) * 2;
            pf[tt][o2]     = *(uint32_t*)&ha;
            pf[tt][o2 + 1] = *(uint32_t*)&hb;
        }

        #pragma unroll
        for (int tt = 0; tt < 4; tt++) {
            #pragma unroll
            for (int jj = 0; jj < 8; jj++) {
                uint32_t vb[4];
                ldsm4(vb, sV + (uint32_t)(jj*16 + laneRB) * VT_ROWB + 2 * (laneCB + tt*16));
                mma_f16(o[2*jj],   pf[tt], &vb[0]);
                mma_f16(o[2*jj+1], pf[tt], &vb[2]);
            }
        }
        __syncthreads();
        buf ^= 1;
    }

    l0 += __shfl_xor_sync(0xffffffffu, l0, 1);
    l0 += __shfl_xor_sync(0xffffffffu, l0, 2);
    l1 += __shfl_xor_sync(0xffffffffu, l1, 1);
    l1 += __shfl_xor_sync(0xffffffffu, l1, 2);
    const float li0 = 1.f / l0, li1 = 1.f / l1;
    const int qr0 = q0 + w*16 + (lane >> 2);
    #pragma unroll
    for (int n = 0; n < 16; n++) {
        const int col = h * DH + n*8 + 2*(lane & 3);
        #pragma unroll
        for (int half = 0; half < 2; half++) {
            const int qr = qr0 + half * 8;
            const float va = o[n][half*2]     * (half ? li1 : li0);
            const float vb2 = o[n][half*2 + 1] * (half ? li1 : li0);
            size_t idx;
            fp16* op;
            if (qr < SVL) { idx = (size_t)(b * SVL + qr) * (HQ*DH) + col; op = a1; }
            else          { idx = (size_t)(b * SEX + qr - SVL) * (HQ*DH) + col; op = a2; }
            *(__half2*)(op + idx) = __floats2half2_rn(va, vb2);
        }
    }
}

// ---------------- launch ----------------
extern "C" void kernel_launch(void* const* d_in, const int* in_sizes, int n_in,
                              void* d_out, int out_size)
{
    (void)in_sizes; (void)n_in; (void)out_size;
    const float* hs_vl  = (const float*)d_in[0];
    const float* hs_ex  = (const float*)d_in[1];
    const int*   posids = (const int*)  d_in[2];
    const float* vl_ln1 = (const float*)d_in[4];
    const float* vl_wq  = (const float*)d_in[5];
    const float* vl_wk  = (const float*)d_in[6];
    const float* vl_wv  = (const float*)d_in[7];
    const float* vl_qn  = (const float*)d_in[8];
    const float* vl_kn  = (const float*)d_in[9];
    const float* vl_wo  = (const float*)d_in[10];
    const float* vl_ln2 = (const float*)d_in[11];
    const float* vl_wg  = (const float*)d_in[12];
    const float* vl_wu  = (const float*)d_in[13];
    const float* vl_wd  = (const float*)d_in[14];
    const float* ex_ln1 = (const float*)d_in[15];
    const float* ex_wq  = (const float*)d_in[16];
    const float* ex_wk  = (const float*)d_in[17];
    const float* ex_wv  = (const float*)d_in[18];
    const float* ex_qn  = (const float*)d_in[19];
    const float* ex_kn  = (const float*)d_in[20];
    const float* ex_wo  = (const float*)d_in[21];
    const float* ex_ln2 = (const float*)d_in[22];
    const float* ex_wg  = (const float*)d_in[23];
    const float* ex_wu  = (const float*)d_in[24];
    const float* ex_wd  = (const float*)d_in[25];

    float* out_vl = (float*)d_out;
    float* out_ex = out_vl + (size_t)MVL * DVL;

#define SYM(T, p, s) T* p; cudaGetSymbolAddress((void**)&p, s)
    SYM(fp16, vl_wqkvT, g_vl_wqkvT); SYM(fp16, ex_wqkvT, g_ex_wqkvT);
    SYM(fp16, vl_woT, g_vl_woT);     SYM(fp16, ex_woT, g_ex_woT);
    SYM(fp16, vl_wguT, g_vl_wguT);   SYM(fp16, ex_wguT, g_ex_wguT);
    SYM(fp16, vl_wdT, g_vl_wdT);     SYM(fp16, ex_wdT, g_ex_wdT);
    SYM(fp16, X1, g_X1); SYM(fp16, X2, g_X2);
    SYM(fp16, A1, g_A1); SYM(fp16, A2, g_A2);
    SYM(fp16, GU1, g_GU1); SYM(fp16, GU2, g_GU2);
    SYM(float, QKV1, g_QKV1); SYM(float, QKV2, g_QKV2);
    SYM(fp16, Qh, g_Qh); SYM(fp16, Kh, g_Kh); SYM(fp16, Vt, g_Vt);
    SYM(float, O1, g_O1); SYM(float, O2, g_O2);
#undef SYM

    cudaFuncSetAttribute(mmagemm_k<0>, cudaFuncAttributeMaxDynamicSharedMemorySize, GEMM_SMEM);
    cudaFuncSetAttribute(mmagemm_k<1>, cudaFuncAttributeMaxDynamicSharedMemorySize, GEMM_SMEM);
    cudaFuncSetAttribute(attn_k, cudaFuncAttributeMaxDynamicSharedMemorySize, ATTN_SMEM);

#define TS(W, T, ROFF, KK, NN, MODE) \
    tsplit_k<<<dim3((NN)/32, (KK)/32), dim3(32, 8)>>>(W, (T) + (size_t)(ROFF)*(KK), KK, NN, MODE)
#define TG(FUSE, AA, BT, Rr, Cc, OH, M, N, K, NOUT) \
    mmagemm_k<FUSE><<<dim3((N)/128, (M)/128), 128, GEMM_SMEM>>>( \
        AA, BT, Rr, Cc, OH, N, K, NOUT)

    // launches 0-2: deps of the big GEMM; launch 3 = VL QKV GEMM (ncu captures idx 3)
    tsplit_qkv_k<<<dim3(4096/32, 2048/32), dim3(32, 8)>>>(vl_wq, vl_wk, vl_wv, vl_wqkvT, 2048);
    rmsnorm_h_k<<<MVL, 256>>>(hs_vl, vl_ln1, X1, DVL);
    rmsnorm_h_k<<<MEX, 256>>>(hs_ex, ex_ln1, X2, DEX);
    TG(0, X1, vl_wqkvT, nullptr, QKV1, (fp16*)nullptr, MVL, 4096, 2048, 0);

    // remaining weight transforms
    tsplit_qkv_k<<<dim3(4096/32, 1024/32), dim3(32, 8)>>>(ex_wq, ex_wk, ex_wv, ex_wqkvT, 1024);
    TS(vl_wo, vl_woT,  0, 2048, 2048, 0);
    TS(ex_wo, ex_woT,  0, 2048, 1024, 0);
    TS(vl_wg, vl_wguT, 0, 2048, 6144, 1);
    TS(vl_wu, vl_wguT, 0, 2048, 6144, 2);
    TS(ex_wg, ex_wguT, 0, 1024, 3072, 1);
    TS(ex_wu, ex_wguT, 0, 1024, 3072, 2);
    TS(vl_wd, vl_wdT,  0, 6144, 2048, 0);
    TS(ex_wd, ex_wdT,  0, 3072, 1024, 0);

    // EX QKV GEMM
    TG(0, X2, ex_wqkvT, nullptr, QKV2, (fp16*)nullptr, MEX, 4096, 1024, 0);

    // head rmsnorm + RoPE -> fp16 Q (pre-scaled), K; V transpose
    qkv_post_k<<<dim3(SVL, HQ,  BB), 128>>>(QKV1,        4096, vl_qn, posids, Qh, HQ,  SVL, 0,   ATT_SCALE);
    qkv_post_k<<<dim3(SEX, HQ,  BB), 128>>>(QKV2,        4096, ex_qn, posids, Qh, HQ,  SEX, SVL, ATT_SCALE);
    qkv_post_k<<<dim3(SVL, HKV, BB), 128>>>(QKV1 + 2048, 4096, vl_kn, posids, Kh, HKV, SVL, 0,   1.0f);
    qkv_post_k<<<dim3(SEX, HKV, BB), 128>>>(QKV2 + 2048, 4096, ex_kn, posids, Kh, HKV, SEX, SVL, 1.0f);
    vtrans_k<<<dim3(SVL/32, DH/32, BB*HKV), dim3(32, 8)>>>(QKV1, 4096, Vt, SVL, 0);
    vtrans_k<<<dim3(SEX/32, DH/32, BB*HKV), dim3(32, 8)>>>(QKV2, 4096, Vt, SEX, SVL);

    // tensor-core attention
    attn_k<<<dim3(SS/64, HQ, BB), 128, ATTN_SMEM>>>(Qh, Kh, Vt, A1, A2);

    // output projection + residual
    TG(0, A1, vl_woT, hs_vl, O1, (fp16*)nullptr, MVL, 2048, 2048, 0);
    TG(0, A2, ex_woT, hs_ex, O2, (fp16*)nullptr, MEX, 1024, 2048, 0);

    // pre-MLP rmsnorm
    rmsnorm_h_k<<<MVL, 256>>>(O1, vl_ln2, X1, DVL);
    rmsnorm_h_k<<<MEX, 256>>>(O2, ex_ln2, X2, DEX);

    // fused gate/up GEMM -> silu(g)*u -> GU
    TG(1, X1, vl_wguT, nullptr, (float*)nullptr, GU1, MVL, 2*IVL, 2048, IVL);
    TG(1, X2, ex_wguT, nullptr, (float*)nullptr, GU2, MEX, 2*IEX, 1024, IEX);

    // down projection + residual -> outputs
    TG(0, GU1, vl_wdT, O1, out_vl, (fp16*)nullptr, MVL, 2048, 6144, 0);
    TG(0, GU2, ex_wdT, O2, out_ex, (fp16*)nullptr, MEX, 1024, 3072, 0);
#undef TS
#undef TG
}

// round 16
// speedup vs baseline: 1.8410x; 1.0486x over previous
#include <cuda_runtime.h>
#include <cuda_fp16.h>
#include <math.h>
#include <stdint.h>

// ---------------- problem constants ----------------
#define BB   4
#define SVL  1024
#define SEX  64
#define SS   1088
#define DVL  2048
#define DEX  1024
#define HQ   16
#define HKV  8
#define DH   128
#define IVL  6144
#define IEX  3072
#define MVL  (BB*SVL)      // 4096
#define MEX  (BB*SEX)      // 256
#define EPSV 1e-6f
#define ATT_SCALE 0.08838834764831845f
#define LOG2_THETA 22.253496664211536f

typedef __half fp16;

// ---------------- low-level helpers ----------------
__device__ __forceinline__ uint32_t smem_u32(const void* p) {
    uint32_t a;
    asm("{ .reg .u64 t; cvta.to.shared.u64 t, %1; cvt.u32.u64 %0, t; }" : "=r"(a) : "l"(p));
    return a;
}
__device__ __forceinline__ void ldsm4(uint32_t* r, uint32_t addr) {
    asm volatile("ldmatrix.sync.aligned.m8n8.x4.shared.b16 {%0,%1,%2,%3}, [%4];"
                 : "=r"(r[0]), "=r"(r[1]), "=r"(r[2]), "=r"(r[3]) : "r"(addr));
}
__device__ __forceinline__ void mma_f16(float* c, const uint32_t* a, const uint32_t* b) {
    asm("mma.sync.aligned.m16n8k16.row.col.f32.f16.f16.f32 "
        "{%0,%1,%2,%3}, {%4,%5,%6,%7}, {%8,%9}, {%0,%1,%2,%3};"
        : "+f"(c[0]), "+f"(c[1]), "+f"(c[2]), "+f"(c[3])
        : "r"(a[0]), "r"(a[1]), "r"(a[2]), "r"(a[3]), "r"(b[0]), "r"(b[1]));
}
__device__ __forceinline__ void cpasync16(uint32_t dst, const void* src) {
    asm volatile("cp.async.cg.shared.global [%0], [%1], 16;" :: "r"(dst), "l"(src));
}
__device__ __forceinline__ float silu_f(float g) {
    return g / (1.f + __expf(-g));
}

// ---------------- device scratch ----------------
__device__ fp16 g_vl_wqkvT[4096u*2048u];
__device__ fp16 g_ex_wqkvT[4096u*1024u];
__device__ fp16 g_vl_woT[2048u*2048u];
__device__ fp16 g_ex_woT[1024u*2048u];
__device__ fp16 g_vl_wguT[12288u*2048u];   // 8-col interleaved g/u packing
__device__ fp16 g_ex_wguT[6144u*1024u];
__device__ fp16 g_vl_wdT[2048u*6144u];
__device__ fp16 g_ex_wdT[1024u*3072u];
__device__ fp16 g_X1[(size_t)MVL*DVL];
__device__ fp16 g_X2[(size_t)MEX*DEX];
__device__ fp16 g_A1[(size_t)MVL*(HQ*DH)];
__device__ fp16 g_A2[(size_t)MEX*(HQ*DH)];
__device__ fp16 g_GU1[(size_t)MVL*IVL];
__device__ fp16 g_GU2[(size_t)MEX*IEX];
__device__ float g_QKV1[(size_t)MVL*4096u];
__device__ float g_QKV2[(size_t)MEX*4096u];
__device__ float g_O1[(size_t)MVL*DVL];
__device__ float g_O2[(size_t)MEX*DEX];
__device__ fp16 g_Qh[(size_t)BB*HQ*SS*DH];
__device__ fp16 g_Kh[(size_t)BB*HKV*SS*DH];
__device__ fp16 g_Vt[(size_t)BB*HKV*DH*SS];

// ---------------- transpose: W[K][N] -> T[N][K] fp16, optional row map ----------
__global__ __launch_bounds__(256) void tsplit_k(const float* __restrict__ W,
                                                fp16* __restrict__ T,
                                                int K, int N, int mode)
{
    __shared__ float t[32][33];
    const int n0 = blockIdx.x * 32, k0 = blockIdx.y * 32;
    const int tx = threadIdx.x, ty = threadIdx.y;
    #pragma unroll
    for (int j = 0; j < 4; j++)
        t[ty + 8 * j][tx] = W[(size_t)(k0 + ty + 8 * j) * N + n0 + tx];
    __syncthreads();
    #pragma unroll
    for (int j = 0; j < 4; j++) {
        const int n = n0 + ty + 8 * j;
        int p = n;
        if (mode == 1) p = ((n >> 3) << 4) | (n & 7);
        else if (mode == 2) p = ((n >> 3) << 4) | 8 | (n & 7);
        T[(size_t)p * K + k0 + tx] = __float2half(t[tx][ty + 8 * j]);
    }
}

// ---------------- merged QKV weight transpose ----------------
__global__ __launch_bounds__(256) void tsplit_qkv_k(const float* __restrict__ Wq,
                                                    const float* __restrict__ Wk,
                                                    const float* __restrict__ Wv,
                                                    fp16* __restrict__ T, int K)
{
    __shared__ float t[32][33];
    const int n0 = blockIdx.x * 32, k0 = blockIdx.y * 32;
    const int tx = threadIdx.x, ty = threadIdx.y;
    const float* W; int nb, Ns;
    if (n0 < 2048)      { W = Wq; nb = n0;        Ns = 2048; }
    else if (n0 < 3072) { W = Wk; nb = n0 - 2048; Ns = 1024; }
    else                { W = Wv; nb = n0 - 3072; Ns = 1024; }
    #pragma unroll
    for (int j = 0; j < 4; j++)
        t[ty + 8 * j][tx] = W[(size_t)(k0 + ty + 8 * j) * Ns + nb + tx];
    __syncthreads();
    #pragma unroll
    for (int j = 0; j < 4; j++)
        T[(size_t)(n0 + ty + 8 * j) * K + k0 + tx] = __float2half(t[tx][ty + 8 * j]);
}

// ---------------- rmsnorm -> fp16 ----------------
__global__ __launch_bounds__(256) void rmsnorm_h_k(const float* __restrict__ x,
                                                   const float* __restrict__ w,
                                                   fp16* __restrict__ y, int D)
{
    const int row = blockIdx.x;
    const float* xr = x + (size_t)row * D;
    float s = 0.f;
    for (int i = threadIdx.x; i < D; i += 256) { float v = xr[i]; s += v * v; }
    #pragma unroll
    for (int o = 16; o; o >>= 1) s += __shfl_xor_sync(0xffffffffu, s, o);
    __shared__ float ws[8];
    if ((threadIdx.x & 31) == 0) ws[threadIdx.x >> 5] = s;
    __syncthreads();
    float tot = 0.f;
    #pragma unroll
    for (int i = 0; i < 8; i++) tot += ws[i];
    const float r = rsqrtf(tot / (float)D + EPSV);
    for (int i = threadIdx.x; i < D; i += 256)
        y[(size_t)row * D + i] = __float2half(xr[i] * r * w[i]);
}

// ---------------- head rmsnorm + RoPE -> fp16 [B,H,SS,DH] ----------------
__global__ __launch_bounds__(128) void qkv_post_k(const float* __restrict__ raw,
                                                  int rowStride,
                                                  const float* __restrict__ w,
                                                  const int* __restrict__ pos_ids,
                                                  fp16* __restrict__ out,
                                                  int H, int sCount, int seqOff,
                                                  float outScale)
{
    __shared__ float sh[DH];
    __shared__ float ws[4];
    const int d = threadIdx.x;
    const int s = blockIdx.x, h = blockIdx.y, b = blockIdx.z;
    const int row = b * sCount + s;
    float v = raw[(size_t)row * rowStride + h * DH + d];
    {
        float v2 = v * v;
        #pragma unroll
        for (int o = 16; o; o >>= 1) v2 += __shfl_xor_sync(0xffffffffu, v2, o);
        if ((d & 31) == 0) ws[d >> 5] = v2;
        __syncthreads();
        float tot = ws[0] + ws[1] + ws[2] + ws[3];
        v = v * rsqrtf(tot * (1.0f / DH) + EPSV) * w[d];
    }
    const int gs = seqOff + s;
    {
        sh[d] = v;
        __syncthreads();
        const float partner = (d < 64) ? -sh[d + 64] : sh[d - 64];
        const int pos = pos_ids[b * SS + gs];
        const float fr = (float)(d & 63) * (1.0f / 64.0f);
        const float invf = exp2f(-fr * LOG2_THETA);
        float sn, cs;
        sincosf((float)pos * invf, &sn, &cs);
        v = v * cs + partner * sn;
    }
    out[(((size_t)b * H + h) * SS + gs) * DH + d] = __float2half(v * outScale);
}

// ---------------- V transpose ----------------
__global__ __launch_bounds__(256) void vtrans_k(const float* __restrict__ qkv, int rowStride,
                                                fp16* __restrict__ Vt, int sCount, int seqOff)
{
    __shared__ float t[32][33];
    const int s0 = blockIdx.x * 32, d0 = blockIdx.y * 32, z = blockIdx.z;
    const int b = z / HKV, h = z - b * HKV;
    const int tx = threadIdx.x, ty = threadIdx.y;
    #pragma unroll
    for (int j = 0; j < 4; j++) {
        const int s = s0 + ty + 8 * j;
        t[ty + 8 * j][tx] = qkv[(size_t)(b * sCount + s) * rowStride + 3072 + h * DH + d0 + tx];
    }
    __syncthreads();
    #pragma unroll
    for (int j = 0; j < 4; j++) {
        const int d = d0 + ty + 8 * j;
        Vt[((size_t)z * DH + d) * SS + seqOff + s0 + tx] = __float2half(t[tx][ty + 8 * j]);
    }
}

// ---------------- fp16 warp-MMA GEMM: C = A @ B^T (+R) --------------------------
// CTA 128x128, 128 threads (4 warps 2x2), warp tile 64x64, KC=64, 3-stage ring.
// 2 CTAs/SM; register double-buffered fragments hide LDS latency.
#define KC 64
#define ROWB 144
#define A_BYTES (128*ROWB)                 // 18432
#define B_BYTES (128*ROWB)                 // 18432
#define STAGE_BYTES (A_BYTES + B_BYTES)    // 36864
#define NSTAGE 3
#define GEMM_SMEM (NSTAGE*STAGE_BYTES)     // 110592 (x2 CTAs = 221184)

__device__ __forceinline__ void g_load_stage(uint32_t sb,
    const fp16* __restrict__ A, const fp16* __restrict__ B,
    int bm, int bn, int K, int k0, int tid)
{
    #pragma unroll
    for (int it = 0; it < 8; it++) {
        const int id = tid + it * 128;
        const int row = id >> 3, col = id & 7;
        cpasync16(sb + (uint32_t)row * ROWB + col * 16,
                  A + (size_t)(bm + row) * K + k0 + col * 8);
    }
    #pragma unroll
    for (int it = 0; it < 8; it++) {
        const int id = tid + it * 128;
        const int row = id >> 3, col = id & 7;
        cpasync16(sb + A_BYTES + (uint32_t)row * ROWB + col * 16,
                  B + (size_t)(bn + row) * K + k0 + col * 8);
    }
    asm volatile("cp.async.commit_group;" ::: "memory");
}

template<int FUSE>
__global__ __launch_bounds__(128, 2)
void mmagemm_k(const fp16* __restrict__ A, const fp16* __restrict__ B,
               const float* __restrict__ R, float* __restrict__ C,
               fp16* __restrict__ oh,
               int N, int K, int Nout)
{
    extern __shared__ char smem[];
    const uint32_t smem_base = smem_u32(smem);
    const int tid = threadIdx.x;
    const int lane = tid & 31, warp = tid >> 5;
    const int wm = warp >> 1, wn = warp & 1;           // 2 x 2 warp grid
    const int bm = blockIdx.y * 128, bn = blockIdx.x * 128;

    float acc[32][4];
    #pragma unroll
    for (int i = 0; i < 32; i++)
        #pragma unroll
        for (int j = 0; j < 4; j++) acc[i][j] = 0.f;

    const int laneRA = (lane & 7) + ((lane >> 3) & 1) * 8;
    const int laneCA = (lane >> 4) * 8;
    const int jmB = lane >> 3;
    const int laneRB = (jmB >> 1) * 8 + (lane & 7);
    const int laneCB = (jmB & 1) * 8;

    // per-warp base byte offsets (kk added at use time)
    const uint32_t baseA = (uint32_t)(wm*64 + laneRA) * ROWB + 2 * laneCA;
    const uint32_t baseB = (uint32_t)A_BYTES + (uint32_t)(wn*64 + laneRB) * ROWB + 2 * laneCB;

    const int nst = K / KC;
    g_load_stage(smem_base, A, B, bm, bn, K, 0, tid);
    g_load_stage(smem_base + STAGE_BYTES, A, B, bm, bn, K, KC, tid);

    uint32_t af[2][4][4], bf[2][4][4];

    for (int s = 0; s < nst; s++) {
        if (s + 2 < nst)
            g_load_stage(smem_base + ((s + 2) % NSTAGE) * STAGE_BYTES,
                         A, B, bm, bn, K, (s + 2) * KC, tid);
        else
            asm volatile("cp.async.commit_group;" ::: "memory");
        asm volatile("cp.async.wait_group 2;" ::: "memory");
        __syncthreads();

        const uint32_t sb = smem_base + (s % NSTAGE) * STAGE_BYTES;

        // prime fragment buffer 0 with kk=0
        #pragma unroll
        for (int i = 0; i < 4; i++)
            ldsm4(af[0][i], sb + baseA + (uint32_t)i*16*ROWB);
        #pragma unroll
        for (int j = 0; j < 4; j++)
            ldsm4(bf[0][j], sb + baseB + (uint32_t)j*16*ROWB);

        #pragma unroll
        for (int kk4 = 0; kk4 < 4; kk4++) {
            const int cur = kk4 & 1;
            if (kk4 < 3) {
                const uint32_t ko = 2u * (uint32_t)((kk4 + 1) * 16);
                #pragma unroll
                for (int i = 0; i < 4; i++)
                    ldsm4(af[cur ^ 1][i], sb + baseA + (uint32_t)i*16*ROWB + ko);
                #pragma unroll
                for (int j = 0; j < 4; j++)
                    ldsm4(bf[cur ^ 1][j], sb + baseB + (uint32_t)j*16*ROWB + ko);
            }
            #pragma unroll
            for (int i = 0; i < 4; i++)
                #pragma unroll
                for (int j = 0; j < 8; j++)
                    mma_f16(acc[i*8 + j], af[cur][i], &bf[cur][j >> 1][(j & 1) * 2]);
        }
        __syncthreads();
    }

    if (!FUSE) {
        #pragma unroll
        for (int i = 0; i < 4; i++) {
            const int mrow = bm + wm*64 + i*16 + (lane >> 2);
            #pragma unroll
            for (int j = 0; j < 8; j++) {
                const int ncol = bn + wn*64 + j*8 + (lane & 3)*2;
                const float* a = acc[i*8 + j];
                const size_t i0 = (size_t)mrow * N + ncol;
                const size_t i1 = (size_t)(mrow + 8) * N + ncol;
                float2 v0 = make_float2(a[0], a[1]);
                float2 v1 = make_float2(a[2], a[3]);
                if (R) {
                    float2 r0 = *(const float2*)(R + i0);
                    float2 r1 = *(const float2*)(R + i1);
                    v0.x += r0.x; v0.y += r0.y;
                    v1.x += r1.x; v1.y += r1.y;
                }
                *(float2*)(C + i0) = v0;
                *(float2*)(C + i1) = v1;
            }
        }
    } else {
        #pragma unroll
        for (int i = 0; i < 4; i++) {
            const int mrow = bm + wm*64 + i*16 + (lane >> 2);
            #pragma unroll
            for (int t = 0; t < 4; t++) {
                const float* g = acc[i*8 + 2*t];
                const float* u = acc[i*8 + 2*t + 1];
                const int ncol = (bn >> 1) + wn*32 + t*8 + (lane & 3)*2;
                const size_t i0 = (size_t)mrow * Nout + ncol;
                const size_t i1 = (size_t)(mrow + 8) * Nout + ncol;
                *(__half2*)(oh + i0) = __floats2half2_rn(silu_f(g[0]) * u[0],
                                                         silu_f(g[1]) * u[1]);
                *(__half2*)(oh + i1) = __floats2half2_rn(silu_f(g[2]) * u[2],
                                                         silu_f(g[3]) * u[3]);
            }
        }
    }
}

// ---------------- tensor-core flash attention ----------------
#define TBK 64
#define QK_ROWB 272
#define VT_ROWB 144
#define QTILE_B (64*QK_ROWB)
#define KTILE_B (64*QK_ROWB)
#define VTILE_B (128*VT_ROWB)
#define AT_STAGE (KTILE_B + VTILE_B)
#define ATTN_SMEM (QTILE_B + 2*AT_STAGE)

__device__ __forceinline__ void attn_load_stage(uint32_t sb, const fp16* __restrict__ Kb,
                                                const fp16* __restrict__ Vb, int k0, int tid)
{
    #pragma unroll
    for (int it = 0; it < 8; it++) {
        const int id = tid + it * 128;
        const int row = id >> 4, col = id & 15;
        cpasync16(sb + (uint32_t)row * QK_ROWB + col * 16,
                  Kb + (size_t)(k0 + row) * DH + col * 8);
    }
    #pragma unroll
    for (int it = 0; it < 8; it++) {
        const int id = tid + it * 128;
        const int row = id >> 3, col = id & 7;
        cpasync16(sb + KTILE_B + (uint32_t)row * VT_ROWB + col * 16,
                  Vb + (size_t)row * SS + k0 + col * 8);
    }
    asm volatile("cp.async.commit_group;" ::: "memory");
}

__global__ __launch_bounds__(128) void attn_k(const fp16* __restrict__ Qg,
                                              const fp16* __restrict__ Kg,
                                              const fp16* __restrict__ Vtg,
                                              fp16* __restrict__ a1, fp16* __restrict__ a2)
{
    extern __shared__ char smem[];
    const uint32_t sQ = smem_u32(smem);
    const int tid = threadIdx.x;
    const int lane = tid & 31, w = tid >> 5;
    const int b = blockIdx.z, h = blockIdx.y;
    const int q0 = blockIdx.x * 64;
    const int kvh = h >> 1;
    const fp16* Qb = Qg + ((size_t)(b * HQ + h) * SS + q0) * DH;
    const fp16* Kb = Kg + (size_t)(b * HKV + kvh) * SS * DH;
    const fp16* Vb = Vtg + (size_t)(b * HKV + kvh) * DH * SS;

    const int nt = (q0 < SVL) ? (SVL / TBK) : (SS / TBK);

    #pragma unroll
    for (int it = 0; it < 8; it++) {
        const int id = tid + it * 128;
        const int row = id >> 4, col = id & 15;
        cpasync16(sQ + (uint32_t)row * QK_ROWB + col * 16, Qb + (size_t)row * DH + col * 8);
    }
    attn_load_stage(sQ + QTILE_B, Kb, Vb, 0, tid);

    const int laneRA = (lane & 7) + ((lane >> 3) & 1) * 8;
    const int laneCA = (lane >> 4) * 8;
    const int jmB = lane >> 3;
    const int laneRB = (jmB >> 1) * 8 + (lane & 7);
    const int laneCB = (jmB & 1) * 8;

    float o[16][4];
    #pragma unroll
    for (int n = 0; n < 16; n++)
        #pragma unroll
        for (int j = 0; j < 4; j++) o[n][j] = 0.f;
    float m0 = -1e30f, m1 = -1e30f, l0 = 0.f, l1 = 0.f;

    int buf = 0;
    for (int t = 0; t < nt; t++) {
        if (t + 1 < nt) {
            attn_load_stage(sQ + QTILE_B + (buf ^ 1) * AT_STAGE, Kb, Vb, (t + 1) * TBK, tid);
            asm volatile("cp.async.wait_group 1;" ::: "memory");
        } else {
            asm volatile("cp.async.wait_group 0;" ::: "memory");
        }
        __syncthreads();

        const uint32_t sK = sQ + QTILE_B + buf * AT_STAGE;
        const uint32_t sV = sK + KTILE_B;
        const int k0 = t * TBK;

        float s[8][4];
        #pragma unroll
        for (int j = 0; j < 8; j++) { s[j][0]=0.f; s[j][1]=0.f; s[j][2]=0.f; s[j][3]=0.f; }
        #pragma unroll
        for (int kk = 0; kk < 8; kk++) {
            uint32_t qa[4];
            ldsm4(qa, sQ + (uint32_t)(w*16 + laneRA) * QK_ROWB + 2 * (laneCA + kk*16));
            #pragma unroll
            for (int jj = 0; jj < 4; jj++) {
                uint32_t kb[4];
                ldsm4(kb, sK + (uint32_t)(jj*16 + laneRB) * QK_ROWB + 2 * (laneCB + kk*16));
                mma_f16(s[2*jj],   qa, &kb[0]);
                mma_f16(s[2*jj+1], qa, &kb[2]);
            }
        }

        if (k0 >= SVL) {
            const int qr0 = q0 + w*16 + (lane >> 2);
            #pragma unroll
            for (int j = 0; j < 8; j++) {
                const int kc = k0 + j*8 + 2*(lane & 3);
                if (kc   > qr0)     s[j][0] = -1e9f;
                if (kc+1 > qr0)     s[j][1] = -1e9f;
                if (kc   > qr0 + 8) s[j][2] = -1e9f;
                if (kc+1 > qr0 + 8) s[j][3] = -1e9f;
            }
        }

        float mx0 = m0, mx1 = m1;
        #pragma unroll
        for (int j = 0; j < 8; j++) {
            mx0 = fmaxf(mx0, fmaxf(s[j][0], s[j][1]));
            mx1 = fmaxf(mx1, fmaxf(s[j][2], s[j][3]));
        }
        mx0 = fmaxf(mx0, __shfl_xor_sync(0xffffffffu, mx0, 1));
        mx0 = fmaxf(mx0, __shfl_xor_sync(0xffffffffu, mx0, 2));
        mx1 = fmaxf(mx1, __shfl_xor_sync(0xffffffffu, mx1, 1));
        mx1 = fmaxf(mx1, __shfl_xor_sync(0xffffffffu, mx1, 2));
        const float corr0 = __expf(m0 - mx0), corr1 = __expf(m1 - mx1);
        m0 = mx0; m1 = mx1;
        l0 *= corr0; l1 *= corr1;
        #pragma unroll
        for (int n = 0; n < 16; n++) {
            o[n][0] *= corr0; o[n][1] *= corr0;
            o[n][2] *= corr1; o[n][3] *= corr1;
        }

        uint32_t pf[4][4];
        #pragma unroll
        for (int j = 0; j < 8; j++) {
            const float p0 = __expf(s[j][0] - mx0);
            const float p1 = __expf(s[j][1] - mx0);
            const float p2 = __expf(s[j][2] - mx1);
            const float p3 = __expf(s[j][3] - mx1);
            l0 += p0 + p1; l1 += p2 + p3;
            __half2 ha = __floats2half2_rn(p0, p1);
            __half2 hb = __floats2half2_rn(p2, p3);
            const int tt = j >> 1, o2 = (j & 1) * 2;
            pf[tt][o2]     = *(uint32_t*)&ha;
            pf[tt][o2 + 1] = *(uint32_t*)&hb;
        }

        #pragma unroll
        for (int tt = 0; tt < 4; tt++) {
            #pragma unroll
            for (int jj = 0; jj < 8; jj++) {
                uint32_t vb[4];
                ldsm4(vb, sV + (uint32_t)(jj*16 + laneRB) * VT_ROWB + 2 * (laneCB + tt*16));
                mma_f16(o[2*jj],   pf[tt], &vb[0]);
                mma_f16(o[2*jj+1], pf[tt], &vb[2]);
            }
        }
        __syncthreads();
        buf ^= 1;
    }

    l0 += __shfl_xor_sync(0xffffffffu, l0, 1);
    l0 += __shfl_xor_sync(0xffffffffu, l0, 2);
    l1 += __shfl_xor_sync(0xffffffffu, l1, 1);
    l1 += __shfl_xor_sync(0xffffffffu, l1, 2);
    const float li0 = 1.f / l0, li1 = 1.f / l1;
    const int qr0 = q0 + w*16 + (lane >> 2);
    #pragma unroll
    for (int n = 0; n < 16; n++) {
        const int col = h * DH + n*8 + 2*(lane & 3);
        #pragma unroll
        for (int half = 0; half < 2; half++) {
            const int qr = qr0 + half * 8;
            const float va = o[n][half*2]     * (half ? li1 : li0);
            const float vb2 = o[n][half*2 + 1] * (half ? li1 : li0);
            size_t idx;
            fp16* op;
            if (qr < SVL) { idx = (size_t)(b * SVL + qr) * (HQ*DH) + col; op = a1; }
            else          { idx = (size_t)(b * SEX + qr - SVL) * (HQ*DH) + col; op = a2; }
            *(__half2*)(op + idx) = __floats2half2_rn(va, vb2);
        }
    }
}

// ---------------- launch ----------------
extern "C" void kernel_launch(void* const* d_in, const int* in_sizes, int n_in,
                              void* d_out, int out_size)
{
    (void)in_sizes; (void)n_in; (void)out_size;
    const float* hs_vl  = (const float*)d_in[0];
    const float* hs_ex  = (const float*)d_in[1];
    const int*   posids = (const int*)  d_in[2];
    const float* vl_ln1 = (const float*)d_in[4];
    const float* vl_wq  = (const float*)d_in[5];
    const float* vl_wk  = (const float*)d_in[6];
    const float* vl_wv  = (const float*)d_in[7];
    const float* vl_qn  = (const float*)d_in[8];
    const float* vl_kn  = (const float*)d_in[9];
    const float* vl_wo  = (const float*)d_in[10];
    const float* vl_ln2 = (const float*)d_in[11];
    const float* vl_wg  = (const float*)d_in[12];
    const float* vl_wu  = (const float*)d_in[13];
    const float* vl_wd  = (const float*)d_in[14];
    const float* ex_ln1 = (const float*)d_in[15];
    const float* ex_wq  = (const float*)d_in[16];
    const float* ex_wk  = (const float*)d_in[17];
    const float* ex_wv  = (const float*)d_in[18];
    const float* ex_qn  = (const float*)d_in[19];
    const float* ex_kn  = (const float*)d_in[20];
    const float* ex_wo  = (const float*)d_in[21];
    const float* ex_ln2 = (const float*)d_in[22];
    const float* ex_wg  = (const float*)d_in[23];
    const float* ex_wu  = (const float*)d_in[24];
    const float* ex_wd  = (const float*)d_in[25];

    float* out_vl = (float*)d_out;
    float* out_ex = out_vl + (size_t)MVL * DVL;

#define SYM(T, p, s) T* p; cudaGetSymbolAddress((void**)&p, s)
    SYM(fp16, vl_wqkvT, g_vl_wqkvT); SYM(fp16, ex_wqkvT, g_ex_wqkvT);
    SYM(fp16, vl_woT, g_vl_woT);     SYM(fp16, ex_woT, g_ex_woT);
    SYM(fp16, vl_wguT, g_vl_wguT);   SYM(fp16, ex_wguT, g_ex_wguT);
    SYM(fp16, vl_wdT, g_vl_wdT);     SYM(fp16, ex_wdT, g_ex_wdT);
    SYM(fp16, X1, g_X1); SYM(fp16, X2, g_X2);
    SYM(fp16, A1, g_A1); SYM(fp16, A2, g_A2);
    SYM(fp16, GU1, g_GU1); SYM(fp16, GU2, g_GU2);
    SYM(float, QKV1, g_QKV1); SYM(float, QKV2, g_QKV2);
    SYM(fp16, Qh, g_Qh); SYM(fp16, Kh, g_Kh); SYM(fp16, Vt, g_Vt);
    SYM(float, O1, g_O1); SYM(float, O2, g_O2);
#undef SYM

    cudaFuncSetAttribute(mmagemm_k<0>, cudaFuncAttributeMaxDynamicSharedMemorySize, GEMM_SMEM);
    cudaFuncSetAttribute(mmagemm_k<1>, cudaFuncAttributeMaxDynamicSharedMemorySize, GEMM_SMEM);
    cudaFuncSetAttribute(attn_k, cudaFuncAttributeMaxDynamicSharedMemorySize, ATTN_SMEM);

#define TS(W, T, ROFF, KK, NN, MODE) \
    tsplit_k<<<dim3((NN)/32, (KK)/32), dim3(32, 8)>>>(W, (T) + (size_t)(ROFF)*(KK), KK, NN, MODE)
#define TG(FUSE, AA, BT, Rr, Cc, OH, M, N, K, NOUT) \
    mmagemm_k<FUSE><<<dim3((N)/128, (M)/128), 128, GEMM_SMEM>>>( \
        AA, BT, Rr, Cc, OH, N, K, NOUT)

    // launches 0-2: deps of the big GEMM; launch 3 = VL QKV GEMM (ncu captures idx 3)
    tsplit_qkv_k<<<dim3(4096/32, 2048/32), dim3(32, 8)>>>(vl_wq, vl_wk, vl_wv, vl_wqkvT, 2048);
    rmsnorm_h_k<<<MVL, 256>>>(hs_vl, vl_ln1, X1, DVL);
    rmsnorm_h_k<<<MEX, 256>>>(hs_ex, ex_ln1, X2, DEX);
    TG(0, X1, vl_wqkvT, nullptr, QKV1, (fp16*)nullptr, MVL, 4096, 2048, 0);

    // remaining weight transforms
    tsplit_qkv_k<<<dim3(4096/32, 1024/32), dim3(32, 8)>>>(ex_wq, ex_wk, ex_wv, ex_wqkvT, 1024);
    TS(vl_wo, vl_woT,  0, 2048, 2048, 0);
    TS(ex_wo, ex_woT,  0, 2048, 1024, 0);
    TS(vl_wg, vl_wguT, 0, 2048, 6144, 1);
    TS(vl_wu, vl_wguT, 0, 2048, 6144, 2);
    TS(ex_wg, ex_wguT, 0, 1024, 3072, 1);
    TS(ex_wu, ex_wguT, 0, 1024, 3072, 2);
    TS(vl_wd, vl_wdT,  0, 6144, 2048, 0);
    TS(ex_wd, ex_wdT,  0, 3072, 1024, 0);

    // EX QKV GEMM
    TG(0, X2, ex_wqkvT, nullptr, QKV2, (fp16*)nullptr, MEX, 4096, 1024, 0);

    // head rmsnorm + RoPE -> fp16 Q (pre-scaled), K; V transpose
    qkv_post_k<<<dim3(SVL, HQ,  BB), 128>>>(QKV1,        4096, vl_qn, posids, Qh, HQ,  SVL, 0,   ATT_SCALE);
    qkv_post_k<<<dim3(SEX, HQ,  BB), 128>>>(QKV2,        4096, ex_qn, posids, Qh, HQ,  SEX, SVL, ATT_SCALE);
    qkv_post_k<<<dim3(SVL, HKV, BB), 128>>>(QKV1 + 2048, 4096, vl_kn, posids, Kh, HKV, SVL, 0,   1.0f);
    qkv_post_k<<<dim3(SEX, HKV, BB), 128>>>(QKV2 + 2048, 4096, ex_kn, posids, Kh, HKV, SEX, SVL, 1.0f);
    vtrans_k<<<dim3(SVL/32, DH/32, BB*HKV), dim3(32, 8)>>>(QKV1, 4096, Vt, SVL, 0);
    vtrans_k<<<dim3(SEX/32, DH/32, BB*HKV), dim3(32, 8)>>>(QKV2, 4096, Vt, SEX, SVL);

    // tensor-core attention
    attn_k<<<dim3(SS/64, HQ, BB), 128, ATTN_SMEM>>>(Qh, Kh, Vt, A1, A2);

    // output projection + residual
    TG(0, A1, vl_woT, hs_vl, O1, (fp16*)nullptr, MVL, 2048, 2048, 0);
    TG(0, A2, ex_woT, hs_ex, O2, (fp16*)nullptr, MEX, 1024, 2048, 0);

    // pre-MLP rmsnorm
    rmsnorm_h_k<<<MVL, 256>>>(O1, vl_ln2, X1, DVL);
    rmsnorm_h_k<<<MEX, 256>>>(O2, ex_ln2, X2, DEX);

    // fused gate/up GEMM -> silu(g)*u -> GU
    TG(1, X1, vl_wguT, nullptr, (float*)nullptr, GU1, MVL, 2*IVL, 2048, IVL);
    TG(1, X2, ex_wguT, nullptr, (float*)nullptr, GU2, MEX, 2*IEX, 1024, IEX);

    // down projection + residual -> outputs
    TG(0, GU1, vl_wdT, O1, out_vl, (fp16*)nullptr, MVL, 2048, 6144, 0);
    TG(0, GU2, ex_wdT, O2, out_ex, (fp16*)nullptr, MEX, 1024, 3072, 0);
#undef TS
#undef TG
}

// round 17
// speedup vs baseline: 1.8451x; 1.0022x over previous
#include <cuda_runtime.h>
#include <cuda_fp16.h>
#include <math.h>
#include <stdint.h>

// ---------------- problem constants ----------------
#define BB   4
#define SVL  1024
#define SEX  64
#define SS   1088
#define DVL  2048
#define DEX  1024
#define HQ   16
#define HKV  8
#define DH   128
#define IVL  6144
#define IEX  3072
#define MVL  (BB*SVL)      // 4096
#define MEX  (BB*SEX)      // 256
#define EPSV 1e-6f
#define ATT_SCALE 0.08838834764831845f
#define LOG2_THETA 22.253496664211536f

typedef __half fp16;

// ---------------- low-level helpers ----------------
__device__ __forceinline__ uint32_t smem_u32(const void* p) {
    uint32_t a;
    asm("{ .reg .u64 t; cvta.to.shared.u64 t, %1; cvt.u32.u64 %0, t; }" : "=r"(a) : "l"(p));
    return a;
}
__device__ __forceinline__ void ldsm4(uint32_t* r, uint32_t addr) {
    asm volatile("ldmatrix.sync.aligned.m8n8.x4.shared.b16 {%0,%1,%2,%3}, [%4];"
                 : "=r"(r[0]), "=r"(r[1]), "=r"(r[2]), "=r"(r[3]) : "r"(addr));
}
__device__ __forceinline__ void mma_f16(float* c, const uint32_t* a, const uint32_t* b) {
    asm("mma.sync.aligned.m16n8k16.row.col.f32.f16.f16.f32 "
        "{%0,%1,%2,%3}, {%4,%5,%6,%7}, {%8,%9}, {%0,%1,%2,%3};"
        : "+f"(c[0]), "+f"(c[1]), "+f"(c[2]), "+f"(c[3])
        : "r"(a[0]), "r"(a[1]), "r"(a[2]), "r"(a[3]), "r"(b[0]), "r"(b[1]));
}
__device__ __forceinline__ void cpasync16(uint32_t dst, const void* src) {
    asm volatile("cp.async.cg.shared.global [%0], [%1], 16;" :: "r"(dst), "l"(src));
}
__device__ __forceinline__ float silu_f(float g) {
    return g / (1.f + __expf(-g));
}

// ---------------- device scratch ----------------
__device__ fp16 g_vl_wqkvT[4096u*2048u];
__device__ fp16 g_ex_wqkvT[4096u*1024u];
__device__ fp16 g_vl_woT[2048u*2048u];
__device__ fp16 g_ex_woT[1024u*2048u];
__device__ fp16 g_vl_wguT[12288u*2048u];   // 8-col interleaved g/u packing
__device__ fp16 g_ex_wguT[6144u*1024u];
__device__ fp16 g_vl_wdT[2048u*6144u];
__device__ fp16 g_ex_wdT[1024u*3072u];
__device__ fp16 g_X1[(size_t)MVL*DVL];
__device__ fp16 g_X2[(size_t)MEX*DEX];
__device__ fp16 g_A1[(size_t)MVL*(HQ*DH)];
__device__ fp16 g_A2[(size_t)MEX*(HQ*DH)];
__device__ fp16 g_GU1[(size_t)MVL*IVL];
__device__ fp16 g_GU2[(size_t)MEX*IEX];
__device__ float g_QKV1[(size_t)MVL*4096u];
__device__ float g_QKV2[(size_t)MEX*4096u];
__device__ float g_O1[(size_t)MVL*DVL];
__device__ float g_O2[(size_t)MEX*DEX];
__device__ fp16 g_Qh[(size_t)BB*HQ*SS*DH];
__device__ fp16 g_Kh[(size_t)BB*HKV*SS*DH];
__device__ fp16 g_Vt[(size_t)BB*HKV*DH*SS];

// ---------------- transpose: W[K][N] -> T[N][K] fp16, 64-wide K tiles, ----------
// uint4 (8xfp16) coalesced stores. optional row map for g/u interleave.
__global__ __launch_bounds__(256) void tsplit_k(const float* __restrict__ W,
                                                fp16* __restrict__ T,
                                                int K, int N, int mode)
{
    __shared__ float t[32][65];
    const int n0 = blockIdx.x * 32, k0 = blockIdx.y * 64;
    const int tx = threadIdx.x, ty = threadIdx.y;   // 32 x 8
    #pragma unroll
    for (int j = 0; j < 8; j++)
        t[tx][ty + 8*j] = W[(size_t)(k0 + ty + 8*j) * N + n0 + tx];
    __syncthreads();
    const int tid = ty * 32 + tx;
    const int n = tid >> 3;
    const int kb = (tid & 7) * 8;
    int p = n0 + n;
    if (mode == 1) p = ((p >> 3) << 4) | (p & 7);
    else if (mode == 2) p = ((p >> 3) << 4) | 8 | (p & 7);
    uint32_t h2[4];
    #pragma unroll
    for (int jj = 0; jj < 4; jj++) {
        __half2 hh = __floats2half2_rn(t[n][kb + 2*jj], t[n][kb + 2*jj + 1]);
        h2[jj] = *(uint32_t*)&hh;
    }
    *(uint4*)&T[(size_t)p * K + k0 + kb] = make_uint4(h2[0], h2[1], h2[2], h2[3]);
}

// ---------------- merged QKV weight transpose (same store scheme) ---------------
__global__ __launch_bounds__(256) void tsplit_qkv_k(const float* __restrict__ Wq,
                                                    const float* __restrict__ Wk,
                                                    const float* __restrict__ Wv,
                                                    fp16* __restrict__ T, int K)
{
    __shared__ float t[32][65];
    const int n0 = blockIdx.x * 32, k0 = blockIdx.y * 64;
    const int tx = threadIdx.x, ty = threadIdx.y;
    const float* W; int nb, Ns;
    if (n0 < 2048)      { W = Wq; nb = n0;        Ns = 2048; }
    else if (n0 < 3072) { W = Wk; nb = n0 - 2048; Ns = 1024; }
    else                { W = Wv; nb = n0 - 3072; Ns = 1024; }
    #pragma unroll
    for (int j = 0; j < 8; j++)
        t[tx][ty + 8*j] = W[(size_t)(k0 + ty + 8*j) * Ns + nb + tx];
    __syncthreads();
    const int tid = ty * 32 + tx;
    const int n = tid >> 3;
    const int kb = (tid & 7) * 8;
    uint32_t h2[4];
    #pragma unroll
    for (int jj = 0; jj < 4; jj++) {
        __half2 hh = __floats2half2_rn(t[n][kb + 2*jj], t[n][kb + 2*jj + 1]);
        h2[jj] = *(uint32_t*)&hh;
    }
    *(uint4*)&T[(size_t)(n0 + n) * K + k0 + kb] = make_uint4(h2[0], h2[1], h2[2], h2[3]);
}

// ---------------- rmsnorm -> fp16 ----------------
__global__ __launch_bounds__(256) void rmsnorm_h_k(const float* __restrict__ x,
                                                   const float* __restrict__ w,
                                                   fp16* __restrict__ y, int D)
{
    const int row = blockIdx.x;
    const float* xr = x + (size_t)row * D;
    float s = 0.f;
    for (int i = threadIdx.x; i < D; i += 256) { float v = xr[i]; s += v * v; }
    #pragma unroll
    for (int o = 16; o; o >>= 1) s += __shfl_xor_sync(0xffffffffu, s, o);
    __shared__ float ws[8];
    if ((threadIdx.x & 31) == 0) ws[threadIdx.x >> 5] = s;
    __syncthreads();
    float tot = 0.f;
    #pragma unroll
    for (int i = 0; i < 8; i++) tot += ws[i];
    const float r = rsqrtf(tot / (float)D + EPSV);
    for (int i = threadIdx.x; i < D; i += 256)
        y[(size_t)row * D + i] = __float2half(xr[i] * r * w[i]);
}

// ---------------- head rmsnorm + RoPE -> fp16 [B,H,SS,DH] ----------------
__global__ __launch_bounds__(128) void qkv_post_k(const float* __restrict__ raw,
                                                  int rowStride,
                                                  const float* __restrict__ w,
                                                  const int* __restrict__ pos_ids,
                                                  fp16* __restrict__ out,
                                                  int H, int sCount, int seqOff,
                                                  float outScale)
{
    __shared__ float sh[DH];
    __shared__ float ws[4];
    const int d = threadIdx.x;
    const int s = blockIdx.x, h = blockIdx.y, b = blockIdx.z;
    const int row = b * sCount + s;
    float v = raw[(size_t)row * rowStride + h * DH + d];
    {
        float v2 = v * v;
        #pragma unroll
        for (int o = 16; o; o >>= 1) v2 += __shfl_xor_sync(0xffffffffu, v2, o);
        if ((d & 31) == 0) ws[d >> 5] = v2;
        __syncthreads();
        float tot = ws[0] + ws[1] + ws[2] + ws[3];
        v = v * rsqrtf(tot * (1.0f / DH) + EPSV) * w[d];
    }
    const int gs = seqOff + s;
    {
        sh[d] = v;
        __syncthreads();
        const float partner = (d < 64) ? -sh[d + 64] : sh[d - 64];
        const int pos = pos_ids[b * SS + gs];
        const float fr = (float)(d & 63) * (1.0f / 64.0f);
        const float invf = exp2f(-fr * LOG2_THETA);
        float sn, cs;
        sincosf((float)pos * invf, &sn, &cs);
        v = v * cs + partner * sn;
    }
    out[(((size_t)b * H + h) * SS + gs) * DH + d] = __float2half(v * outScale);
}

// ---------------- V transpose ----------------
__global__ __launch_bounds__(256) void vtrans_k(const float* __restrict__ qkv, int rowStride,
                                                fp16* __restrict__ Vt, int sCount, int seqOff)
{
    __shared__ float t[32][33];
    const int s0 = blockIdx.x * 32, d0 = blockIdx.y * 32, z = blockIdx.z;
    const int b = z / HKV, h = z - b * HKV;
    const int tx = threadIdx.x, ty = threadIdx.y;
    #pragma unroll
    for (int j = 0; j < 4; j++) {
        const int s = s0 + ty + 8 * j;
        t[ty + 8 * j][tx] = qkv[(size_t)(b * sCount + s) * rowStride + 3072 + h * DH + d0 + tx];
    }
    __syncthreads();
    #pragma unroll
    for (int j = 0; j < 4; j++) {
        const int d = d0 + ty + 8 * j;
        Vt[((size_t)z * DH + d) * SS + seqOff + s0 + tx] = __float2half(t[tx][ty + 8 * j]);
    }
}

// ---------------- fp16 warp-MMA GEMM: C = A @ B^T (+R) --------------------------
// CTA 128x128, 128 threads (4 warps 2x2), warp tile 64x64, KC=64, 3-stage ring.
// 2 CTAs/SM; register double-buffered fragments hide LDS latency.
#define KC 64
#define ROWB 144
#define A_BYTES (128*ROWB)                 // 18432
#define B_BYTES (128*ROWB)                 // 18432
#define STAGE_BYTES (A_BYTES + B_BYTES)    // 36864
#define NSTAGE 3
#define GEMM_SMEM (NSTAGE*STAGE_BYTES)     // 110592 (x2 CTAs = 221184)

__device__ __forceinline__ void g_load_stage(uint32_t sb,
    const fp16* __restrict__ A, const fp16* __restrict__ B,
    int bm, int bn, int K, int k0, int tid)
{
    #pragma unroll
    for (int it = 0; it < 8; it++) {
        const int id = tid + it * 128;
        const int row = id >> 3, col = id & 7;
        cpasync16(sb + (uint32_t)row * ROWB + col * 16,
                  A + (size_t)(bm + row) * K + k0 + col * 8);
    }
    #pragma unroll
    for (int it = 0; it < 8; it++) {
        const int id = tid + it * 128;
        const int row = id >> 3, col = id & 7;
        cpasync16(sb + A_BYTES + (uint32_t)row * ROWB + col * 16,
                  B + (size_t)(bn + row) * K + k0 + col * 8);
    }
    asm volatile("cp.async.commit_group;" ::: "memory");
}

template<int FUSE>
__global__ __launch_bounds__(128, 2)
void mmagemm_k(const fp16* __restrict__ A, const fp16* __restrict__ B,
               const float* __restrict__ R, float* __restrict__ C,
               fp16* __restrict__ oh,
               int N, int K, int Nout)
{
    extern __shared__ char smem[];
    const uint32_t smem_base = smem_u32(smem);
    const int tid = threadIdx.x;
    const int lane = tid & 31, warp = tid >> 5;
    const int wm = warp >> 1, wn = warp & 1;           // 2 x 2 warp grid
    const int bm = blockIdx.y * 128, bn = blockIdx.x * 128;

    float acc[32][4];
    #pragma unroll
    for (int i = 0; i < 32; i++)
        #pragma unroll
        for (int j = 0; j < 4; j++) acc[i][j] = 0.f;

    const int laneRA = (lane & 7) + ((lane >> 3) & 1) * 8;
    const int laneCA = (lane >> 4) * 8;
    const int jmB = lane >> 3;
    const int laneRB = (jmB >> 1) * 8 + (lane & 7);
    const int laneCB = (jmB & 1) * 8;

    const uint32_t baseA = (uint32_t)(wm*64 + laneRA) * ROWB + 2 * laneCA;
    const uint32_t baseB = (uint32_t)A_BYTES + (uint32_t)(wn*64 + laneRB) * ROWB + 2 * laneCB;

    const int nst = K / KC;
    g_load_stage(smem_base, A, B, bm, bn, K, 0, tid);
    g_load_stage(smem_base + STAGE_BYTES, A, B, bm, bn, K, KC, tid);

    uint32_t af[2][4][4], bf[2][4][4];

    for (int s = 0; s < nst; s++) {
        if (s + 2 < nst)
            g_load_stage(smem_base + ((s + 2) % NSTAGE) * STAGE_BYTES,
                         A, B, bm, bn, K, (s + 2) * KC, tid);
        else
            asm volatile("cp.async.commit_group;" ::: "memory");
        asm volatile("cp.async.wait_group 2;" ::: "memory");
        __syncthreads();

        const uint32_t sb = smem_base + (s % NSTAGE) * STAGE_BYTES;

        #pragma unroll
        for (int i = 0; i < 4; i++)
            ldsm4(af[0][i], sb + baseA + (uint32_t)i*16*ROWB);
        #pragma unroll
        for (int j = 0; j < 4; j++)
            ldsm4(bf[0][j], sb + baseB + (uint32_t)j*16*ROWB);

        #pragma unroll
        for (int kk4 = 0; kk4 < 4; kk4++) {
            const int cur = kk4 & 1;
            if (kk4 < 3) {
                const uint32_t ko = 2u * (uint32_t)((kk4 + 1) * 16);
                #pragma unroll
                for (int i = 0; i < 4; i++)
                    ldsm4(af[cur ^ 1][i], sb + baseA + (uint32_t)i*16*ROWB + ko);
                #pragma unroll
                for (int j = 0; j < 4; j++)
                    ldsm4(bf[cur ^ 1][j], sb + baseB + (uint32_t)j*16*ROWB + ko);
            }
            #pragma unroll
            for (int i = 0; i < 4; i++)
                #pragma unroll
                for (int j = 0; j < 8; j++)
                    mma_f16(acc[i*8 + j], af[cur][i], &bf[cur][j >> 1][(j & 1) * 2]);
        }
        __syncthreads();
    }

    if (!FUSE) {
        #pragma unroll
        for (int i = 0; i < 4; i++) {
            const int mrow = bm + wm*64 + i*16 + (lane >> 2);
            #pragma unroll
            for (int j = 0; j < 8; j++) {
                const int ncol = bn + wn*64 + j*8 + (lane & 3)*2;
                const float* a = acc[i*8 + j];
                const size_t i0 = (size_t)mrow * N + ncol;
                const size_t i1 = (size_t)(mrow + 8) * N + ncol;
                float2 v0 = make_float2(a[0], a[1]);
                float2 v1 = make_float2(a[2], a[3]);
                if (R) {
                    float2 r0 = *(const float2*)(R + i0);
                    float2 r1 = *(const float2*)(R + i1);
                    v0.x += r0.x; v0.y += r0.y;
                    v1.x += r1.x; v1.y += r1.y;
                }
                *(float2*)(C + i0) = v0;
                *(float2*)(C + i1) = v1;
            }
        }
    } else {
        #pragma unroll
        for (int i = 0; i < 4; i++) {
            const int mrow = bm + wm*64 + i*16 + (lane >> 2);
            #pragma unroll
            for (int t = 0; t < 4; t++) {
                const float* g = acc[i*8 + 2*t];
                const float* u = acc[i*8 + 2*t + 1];
                const int ncol = (bn >> 1) + wn*32 + t*8 + (lane & 3)*2;
                const size_t i0 = (size_t)mrow * Nout + ncol;
                const size_t i1 = (size_t)(mrow + 8) * Nout + ncol;
                *(__half2*)(oh + i0) = __floats2half2_rn(silu_f(g[0]) * u[0],
                                                         silu_f(g[1]) * u[1]);
                *(__half2*)(oh + i1) = __floats2half2_rn(silu_f(g[2]) * u[2],
                                                         silu_f(g[3]) * u[3]);
            }
        }
    }
}

// ---------------- tensor-core flash attention (fragment double-buffered) --------
#define TBK 64
#define QK_ROWB 272
#define VT_ROWB 144
#define QTILE_B (64*QK_ROWB)
#define KTILE_B (64*QK_ROWB)
#define VTILE_B (128*VT_ROWB)
#define AT_STAGE (KTILE_B + VTILE_B)
#define ATTN_SMEM (QTILE_B + 2*AT_STAGE)

__device__ __forceinline__ void attn_load_stage(uint32_t sb, const fp16* __restrict__ Kb,
                                                const fp16* __restrict__ Vb, int k0, int tid)
{
    #pragma unroll
    for (int it = 0; it < 8; it++) {
        const int id = tid + it * 128;
        const int row = id >> 4, col = id & 15;
        cpasync16(sb + (uint32_t)row * QK_ROWB + col * 16,
                  Kb + (size_t)(k0 + row) * DH + col * 8);
    }
    #pragma unroll
    for (int it = 0; it < 8; it++) {
        const int id = tid + it * 128;
        const int row = id >> 3, col = id & 7;
        cpasync16(sb + KTILE_B + (uint32_t)row * VT_ROWB + col * 16,
                  Vb + (size_t)row * SS + k0 + col * 8);
    }
    asm volatile("cp.async.commit_group;" ::: "memory");
}

__global__ __launch_bounds__(128) void attn_k(const fp16* __restrict__ Qg,
                                              const fp16* __restrict__ Kg,
                                              const fp16* __restrict__ Vtg,
                                              fp16* __restrict__ a1, fp16* __restrict__ a2)
{
    extern __shared__ char smem[];
    const uint32_t sQ = smem_u32(smem);
    const int tid = threadIdx.x;
    const int lane = tid & 31, w = tid >> 5;
    const int b = blockIdx.z, h = blockIdx.y;
    const int q0 = blockIdx.x * 64;
    const int kvh = h >> 1;
    const fp16* Qb = Qg + ((size_t)(b * HQ + h) * SS + q0) * DH;
    const fp16* Kb = Kg + (size_t)(b * HKV + kvh) * SS * DH;
    const fp16* Vb = Vtg + (size_t)(b * HKV + kvh) * DH * SS;

    const int nt = (q0 < SVL) ? (SVL / TBK) : (SS / TBK);

    #pragma unroll
    for (int it = 0; it < 8; it++) {
        const int id = tid + it * 128;
        const int row = id >> 4, col = id & 15;
        cpasync16(sQ + (uint32_t)row * QK_ROWB + col * 16, Qb + (size_t)row * DH + col * 8);
    }
    attn_load_stage(sQ + QTILE_B, Kb, Vb, 0, tid);

    const int laneRA = (lane & 7) + ((lane >> 3) & 1) * 8;
    const int laneCA = (lane >> 4) * 8;
    const int jmB = lane >> 3;
    const int laneRB = (jmB >> 1) * 8 + (lane & 7);
    const int laneCB = (jmB & 1) * 8;

    const uint32_t baseQ = (uint32_t)(w*16 + laneRA) * QK_ROWB + 2 * laneCA;

    float o[16][4];
    #pragma unroll
    for (int n = 0; n < 16; n++)
        #pragma unroll
        for (int j = 0; j < 4; j++) o[n][j] = 0.f;
    float m0 = -1e30f, m1 = -1e30f, l0 = 0.f, l1 = 0.f;

    int buf = 0;
    for (int t = 0; t < nt; t++) {
        if (t + 1 < nt) {
            attn_load_stage(sQ + QTILE_B + (buf ^ 1) * AT_STAGE, Kb, Vb, (t + 1) * TBK, tid);
            asm volatile("cp.async.wait_group 1;" ::: "memory");
        } else {
            asm volatile("cp.async.wait_group 0;" ::: "memory");
        }
        __syncthreads();

        const uint32_t sK = sQ + QTILE_B + buf * AT_STAGE;
        const uint32_t sV = sK + KTILE_B;
        const int k0 = t * TBK;

        // ---- S = Q @ K^T, fragment double-buffered over kk ----
        float s[8][4];
        #pragma unroll
        for (int j = 0; j < 8; j++) { s[j][0]=0.f; s[j][1]=0.f; s[j][2]=0.f; s[j][3]=0.f; }
        uint32_t qa[2][4], kb[2][4][4];
        ldsm4(qa[0], sQ + baseQ);
        #pragma unroll
        for (int jj = 0; jj < 4; jj++)
            ldsm4(kb[0][jj], sK + (uint32_t)(jj*16 + laneRB) * QK_ROWB + 2 * laneCB);
        #pragma unroll
        for (int kk = 0; kk < 8; kk++) {
            const int cur = kk & 1;
            if (kk < 7) {
                const uint32_t ko = 2u * (uint32_t)((kk + 1) * 16);
                ldsm4(qa[cur ^ 1], sQ + baseQ + ko);
                #pragma unroll
                for (int jj = 0; jj < 4; jj++)
                    ldsm4(kb[cur ^ 1][jj], sK + (uint32_t)(jj*16 + laneRB) * QK_ROWB
                                              + 2 * laneCB + ko);
            }
            #pragma unroll
            for (int jj = 0; jj < 4; jj++) {
                mma_f16(s[2*jj],   qa[cur], &kb[cur][jj][0]);
                mma_f16(s[2*jj+1], qa[cur], &kb[cur][jj][2]);
            }
        }

        if (k0 >= SVL) {
            const int qr0 = q0 + w*16 + (lane >> 2);
            #pragma unroll
            for (int j = 0; j < 8; j++) {
                const int kc = k0 + j*8 + 2*(lane & 3);
                if (kc   > qr0)     s[j][0] = -1e9f;
                if (kc+1 > qr0)     s[j][1] = -1e9f;
                if (kc   > qr0 + 8) s[j][2] = -1e9f;
                if (kc+1 > qr0 + 8) s[j][3] = -1e9f;
            }
        }

        float mx0 = m0, mx1 = m1;
        #pragma unroll
        for (int j = 0; j < 8; j++) {
            mx0 = fmaxf(mx0, fmaxf(s[j][0], s[j][1]));
            mx1 = fmaxf(mx1, fmaxf(s[j][2], s[j][3]));
        }
        mx0 = fmaxf(mx0, __shfl_xor_sync(0xffffffffu, mx0, 1));
        mx0 = fmaxf(mx0, __shfl_xor_sync(0xffffffffu, mx0, 2));
        mx1 = fmaxf(mx1, __shfl_xor_sync(0xffffffffu, mx1, 1));
        mx1 = fmaxf(mx1, __shfl_xor_sync(0xffffffffu, mx1, 2));
        const float corr0 = __expf(m0 - mx0), corr1 = __expf(m1 - mx1);
        m0 = mx0; m1 = mx1;
        l0 *= corr0; l1 *= corr1;
        #pragma unroll
        for (int n = 0; n < 16; n++) {
            o[n][0] *= corr0; o[n][1] *= corr0;
            o[n][2] *= corr1; o[n][3] *= corr1;
        }

        uint32_t pf[4][4];
        #pragma unroll
        for (int j = 0; j < 8; j++) {
            const float p0 = __expf(s[j][0] - mx0);
            const float p1 = __expf(s[j][1] - mx0);
            const float p2 = __expf(s[j][2] - mx1);
            const float p3 = __expf(s[j][3] - mx1);
            l0 += p0 + p1; l1 += p2 + p3;
            __half2 ha = __floats2half2_rn(p0, p1);
            __half2 hb = __floats2half2_rn(p2, p3);
            const int tt = j >> 1, o2 = (j & 1) * 2;
            pf[tt][o2]     = *(uint32_t*)&ha;
            pf[tt][o2 + 1] = *(uint32_t*)&hb;
        }

        // ---- O += P @ V, fragment double-buffered over tt ----
        {
            uint32_t vb[2][8][4];
            #pragma unroll
            for (int jj = 0; jj < 8; jj++)
                ldsm4(vb[0][jj], sV + (uint32_t)(jj*16 + laneRB) * VT_ROWB + 2 * laneCB);
            #pragma unroll
            for (int tt = 0; tt < 4; tt++) {
                const int cur = tt & 1;
                if (tt < 3) {
                    const uint32_t ko = 2u * (uint32_t)((tt + 1) * 16);
                    #pragma unroll
                    for (int jj = 0; jj < 8; jj++)
                        ldsm4(vb[cur ^ 1][jj], sV + (uint32_t)(jj*16 + laneRB) * VT_ROWB
                                                  + 2 * laneCB + ko);
                }
                #pragma unroll
                for (int jj = 0; jj < 8; jj++) {
                    mma_f16(o[2*jj],   pf[tt], &vb[cur][jj][0]);
                    mma_f16(o[2*jj+1], pf[tt], &vb[cur][jj][2]);
                }
            }
        }
        __syncthreads();
        buf ^= 1;
    }

    l0 += __shfl_xor_sync(0xffffffffu, l0, 1);
    l0 += __shfl_xor_sync(0xffffffffu, l0, 2);
    l1 += __shfl_xor_sync(0xffffffffu, l1, 1);
    l1 += __shfl_xor_sync(0xffffffffu, l1, 2);
    const float li0 = 1.f / l0, li1 = 1.f / l1;
    const int qr0 = q0 + w*16 + (lane >> 2);
    #pragma unroll
    for (int n = 0; n < 16; n++) {
        const int col = h * DH + n*8 + 2*(lane & 3);
        #pragma unroll
        for (int half = 0; half < 2; half++) {
            const int qr = qr0 + half * 8;
            const float va = o[n][half*2]     * (half ? li1 : li0);
            const float vb2 = o[n][half*2 + 1] * (half ? li1 : li0);
            size_t idx;
            fp16* op;
            if (qr < SVL) { idx = (size_t)(b * SVL + qr) * (HQ*DH) + col; op = a1; }
            else          { idx = (size_t)(b * SEX + qr - SVL) * (HQ*DH) + col; op = a2; }
            *(__half2*)(op + idx) = __floats2half2_rn(va, vb2);
        }
    }
}

// ---------------- launch ----------------
extern "C" void kernel_launch(void* const* d_in, const int* in_sizes, int n_in,
                              void* d_out, int out_size)
{
    (void)in_sizes; (void)n_in; (void)out_size;
    const float* hs_vl  = (const float*)d_in[0];
    const float* hs_ex  = (const float*)d_in[1];
    const int*   posids = (const int*)  d_in[2];
    const float* vl_ln1 = (const float*)d_in[4];
    const float* vl_wq  = (const float*)d_in[5];
    const float* vl_wk  = (const float*)d_in[6];
    const float* vl_wv  = (const float*)d_in[7];
    const float* vl_qn  = (const float*)d_in[8];
    const float* vl_kn  = (const float*)d_in[9];
    const float* vl_wo  = (const float*)d_in[10];
    const float* vl_ln2 = (const float*)d_in[11];
    const float* vl_wg  = (const float*)d_in[12];
    const float* vl_wu  = (const float*)d_in[13];
    const float* vl_wd  = (const float*)d_in[14];
    const float* ex_ln1 = (const float*)d_in[15];
    const float* ex_wq  = (const float*)d_in[16];
    const float* ex_wk  = (const float*)d_in[17];
    const float* ex_wv  = (const float*)d_in[18];
    const float* ex_qn  = (const float*)d_in[19];
    const float* ex_kn  = (const float*)d_in[20];
    const float* ex_wo  = (const float*)d_in[21];
    const float* ex_ln2 = (const float*)d_in[22];
    const float* ex_wg  = (const float*)d_in[23];
    const float* ex_wu  = (const float*)d_in[24];
    const float* ex_wd  = (const float*)d_in[25];

    float* out_vl = (float*)d_out;
    float* out_ex = out_vl + (size_t)MVL * DVL;

#define SYM(T, p, s) T* p; cudaGetSymbolAddress((void**)&p, s)
    SYM(fp16, vl_wqkvT, g_vl_wqkvT); SYM(fp16, ex_wqkvT, g_ex_wqkvT);
    SYM(fp16, vl_woT, g_vl_woT);     SYM(fp16, ex_woT, g_ex_woT);
    SYM(fp16, vl_wguT, g_vl_wguT);   SYM(fp16, ex_wguT, g_ex_wguT);
    SYM(fp16, vl_wdT, g_vl_wdT);     SYM(fp16, ex_wdT, g_ex_wdT);
    SYM(fp16, X1, g_X1); SYM(fp16, X2, g_X2);
    SYM(fp16, A1, g_A1); SYM(fp16, A2, g_A2);
    SYM(fp16, GU1, g_GU1); SYM(fp16, GU2, g_GU2);
    SYM(float, QKV1, g_QKV1); SYM(float, QKV2, g_QKV2);
    SYM(fp16, Qh, g_Qh); SYM(fp16, Kh, g_Kh); SYM(fp16, Vt, g_Vt);
    SYM(float, O1, g_O1); SYM(float, O2, g_O2);
#undef SYM

    cudaFuncSetAttribute(mmagemm_k<0>, cudaFuncAttributeMaxDynamicSharedMemorySize, GEMM_SMEM);
    cudaFuncSetAttribute(mmagemm_k<1>, cudaFuncAttributeMaxDynamicSharedMemorySize, GEMM_SMEM);
    cudaFuncSetAttribute(attn_k, cudaFuncAttributeMaxDynamicSharedMemorySize, ATTN_SMEM);

#define TS(W, T, ROFF, KK, NN, MODE) \
    tsplit_k<<<dim3((NN)/32, (KK)/64), dim3(32, 8)>>>(W, (T) + (size_t)(ROFF)*(KK), KK, NN, MODE)
#define TG(FUSE, AA, BT, Rr, Cc, OH, M, N, K, NOUT) \
    mmagemm_k<FUSE><<<dim3((N)/128, (M)/128), 128, GEMM_SMEM>>>( \
        AA, BT, Rr, Cc, OH, N, K, NOUT)

    // launches 0-2: deps of the big GEMM; launch 3 = VL QKV GEMM (ncu captures idx 3)
    tsplit_qkv_k<<<dim3(4096/32, 2048/64), dim3(32, 8)>>>(vl_wq, vl_wk, vl_wv, vl_wqkvT, 2048);
    rmsnorm_h_k<<<MVL, 256>>>(hs_vl, vl_ln1, X1, DVL);
    rmsnorm_h_k<<<MEX, 256>>>(hs_ex, ex_ln1, X2, DEX);
    TG(0, X1, vl_wqkvT, nullptr, QKV1, (fp16*)nullptr, MVL, 4096, 2048, 0);

    // remaining weight transforms
    tsplit_qkv_k<<<dim3(4096/32, 1024/64), dim3(32, 8)>>>(ex_wq, ex_wk, ex_wv, ex_wqkvT, 1024);
    TS(vl_wo, vl_woT,  0, 2048, 2048, 0);
    TS(ex_wo, ex_woT,  0, 2048, 1024, 0);
    TS(vl_wg, vl_wguT, 0, 2048, 6144, 1);
    TS(vl_wu, vl_wguT, 0, 2048, 6144, 2);
    TS(ex_wg, ex_wguT, 0, 1024, 3072, 1);
    TS(ex_wu, ex_wguT, 0, 1024, 3072, 2);
    TS(vl_wd, vl_wdT,  0, 6144, 2048, 0);
    TS(ex_wd, ex_wdT,  0, 3072, 1024, 0);

    // EX QKV GEMM
    TG(0, X2, ex_wqkvT, nullptr, QKV2, (fp16*)nullptr, MEX, 4096, 1024, 0);

    // head rmsnorm + RoPE -> fp16 Q (pre-scaled), K; V transpose
    qkv_post_k<<<dim3(SVL, HQ,  BB), 128>>>(QKV1,        4096, vl_qn, posids, Qh, HQ,  SVL, 0,   ATT_SCALE);
    qkv_post_k<<<dim3(SEX, HQ,  BB), 128>>>(QKV2,        4096, ex_qn, posids, Qh, HQ,  SEX, SVL, ATT_SCALE);
    qkv_post_k<<<dim3(SVL, HKV, BB), 128>>>(QKV1 + 2048, 4096, vl_kn, posids, Kh, HKV, SVL, 0,   1.0f);
    qkv_post_k<<<dim3(SEX, HKV, BB), 128>>>(QKV2 + 2048, 4096, ex_kn, posids, Kh, HKV, SEX, SVL, 1.0f);
    vtrans_k<<<dim3(SVL/32, DH/32, BB*HKV), dim3(32, 8)>>>(QKV1, 4096, Vt, SVL, 0);
    vtrans_k<<<dim3(SEX/32, DH/32, BB*HKV), dim3(32, 8)>>>(QKV2, 4096, Vt, SEX, SVL);

    // tensor-core attention
    attn_k<<<dim3(SS/64, HQ, BB), 128, ATTN_SMEM>>>(Qh, Kh, Vt, A1, A2);

    // output projection + residual
    TG(0, A1, vl_woT, hs_vl, O1, (fp16*)nullptr, MVL, 2048, 2048, 0);
    TG(0, A2, ex_woT, hs_ex, O2, (fp16*)nullptr, MEX, 1024, 2048, 0);

    // pre-MLP rmsnorm
    rmsnorm_h_k<<<MVL, 256>>>(O1, vl_ln2, X1, DVL);
    rmsnorm_h_k<<<MEX, 256>>>(O2, ex_ln2, X2, DEX);

    // fused gate/up GEMM -> silu(g)*u -> GU
    TG(1, X1, vl_wguT, nullptr, (float*)nullptr, GU1, MVL, 2*IVL, 2048, IVL);
    TG(1, X2, ex_wguT, nullptr, (float*)nullptr, GU2, MEX, 2*IEX, 1024, IEX);

    // down projection + residual -> outputs
    TG(0, GU1, vl_wdT, O1, out_vl, (fp16*)nullptr, MVL, 2048, 6144, 0);
    TG(0, GU2, ex_wdT, O2, out_ex, (fp16*)nullptr, MEX, 1024, 3072, 0);
#undef TS
#undef TG
}